// round 3
// baseline (speedup 1.0000x reference)
#include <cuda_runtime.h>
#include <cuda_fp16.h>
#include <math.h>

#define B_   2
#define S_   2048
#define D_   1024
#define H_   16
#define DH_  64
#define M_   (B_*S_)          // 4096 tokens
#define BH_  (B_*H_)          // 32
#define KK_  512              // top-k
#define MCH_ 16               // mean chunks
#define GH_  4                // heads per L2-resident group

#define SA   40               // smem row stride (halves) for 32-col tiles
#define SBP  136              // smem row stride for 128-col B tiles
#define SBV  72               // smem row stride for 64-col V tiles

// ---------------- scratch (static device memory; no allocations) ----------------
__device__ __half g_xh[M_*D_];
__device__ __half g_Wqh[D_*D_];
__device__ __half g_Wkh[D_*D_];
__device__ __half g_Wvh[D_*D_];
__device__ __half g_Wgh[D_*D_];
__device__ __half g_Woh[D_*D_];
__device__ __half g_qh[M_*D_];
__device__ __half g_kh[M_*D_];
__device__ __half g_vh16[M_*D_];
__device__ __half g_gateh[M_*D_];
__device__ __half g_qnh[M_*D_];     // [BH][S][DH]
__device__ __half g_knh[M_*D_];     // [BH][S][DH]
__device__ __half g_vhh[M_*D_];     // [BH][S][DH]
__device__ __half g_obsdh[M_*D_];   // attention output in [B,S,D]
__device__ __half g_out2h[M_*D_];   // after Wo
__device__ float  g_scores[(size_t)GH_*S_*S_];   // 64MB fp32 scores (reused per group)
__device__ __half g_attnh[(size_t)GH_*S_*S_];    // 32MB fp16 weights (reused per group)
__device__ float  g_xpart[MCH_*B_*D_];
__device__ float  g_xmean[B_*D_];
__device__ float  g_temp[B_];

// ---------------- mma / ldmatrix helpers ----------------
__device__ __forceinline__ void mma_f16(float* d, const unsigned* a, unsigned b0, unsigned b1){
    asm volatile("mma.sync.aligned.m16n8k16.row.col.f32.f16.f16.f32 "
        "{%0,%1,%2,%3}, {%4,%5,%6,%7}, {%8,%9}, {%0,%1,%2,%3};\n"
        : "+f"(d[0]),"+f"(d[1]),"+f"(d[2]),"+f"(d[3])
        : "r"(a[0]),"r"(a[1]),"r"(a[2]),"r"(a[3]), "r"(b0),"r"(b1));
}
__device__ __forceinline__ void ldsm4(unsigned* r, const __half* p){
    unsigned addr = (unsigned)__cvta_generic_to_shared(p);
    asm volatile("ldmatrix.sync.aligned.m8n8.x4.shared.b16 {%0,%1,%2,%3}, [%4];\n"
        :"=r"(r[0]),"=r"(r[1]),"=r"(r[2]),"=r"(r[3]) : "r"(addr));
}
__device__ __forceinline__ void ldsm4t(unsigned* r, const __half* p){
    unsigned addr = (unsigned)__cvta_generic_to_shared(p);
    asm volatile("ldmatrix.sync.aligned.m8n8.x4.trans.shared.b16 {%0,%1,%2,%3}, [%4];\n"
        :"=r"(r[0]),"=r"(r[1]),"=r"(r[2]),"=r"(r[3]) : "r"(addr));
}

// ---------------- fp32 -> fp16 conversion ----------------
__global__ __launch_bounds__(256) void f2h_kernel(const float* __restrict__ in,
                                                  __half* __restrict__ out){
    int i = blockIdx.x*256 + threadIdx.x;
    float4 v = reinterpret_cast<const float4*>(in)[i];
    reinterpret_cast<__half2*>(out)[2*i]   = __floats2half2_rn(v.x, v.y);
    reinterpret_cast<__half2*>(out)[2*i+1] = __floats2half2_rn(v.z, v.w);
}

// ---------------- mean over sequence (2-stage, deterministic) ----------------
__global__ __launch_bounds__(256) void mean_stage1(const float* __restrict__ x){
    int b  = blockIdx.x / MCH_;
    int ch = blockIdx.x % MCH_;
    int s0 = ch * (S_/MCH_);
    int tid = threadIdx.x;
    float acc[4] = {0.f,0.f,0.f,0.f};
    for (int s = s0; s < s0 + S_/MCH_; ++s){
        const float* xp = x + ((size_t)(b*S_+s))*D_;
        #pragma unroll
        for (int j = 0; j < 4; ++j) acc[j] += xp[tid + j*256];
    }
    #pragma unroll
    for (int j = 0; j < 4; ++j) g_xpart[((size_t)ch*B_ + b)*D_ + tid + j*256] = acc[j];
}

__global__ __launch_bounds__(256) void mean_stage2(){
    int idx = blockIdx.x*256 + threadIdx.x;
    int b = idx / D_, d = idx % D_;
    float s = 0.f;
    #pragma unroll
    for (int ch = 0; ch < MCH_; ++ch) s += g_xpart[((size_t)ch*B_ + b)*D_ + d];
    g_xmean[idx] = s * (1.0f/S_);
}

__global__ __launch_bounds__(256) void temp_kernel(const float* __restrict__ Wt,
                                                   const float* __restrict__ bt){
    __shared__ float red[256];
    int b = blockIdx.x, tid = threadIdx.x;
    float s = 0.f;
    for (int d = tid; d < D_; d += 256) s += g_xmean[b*D_ + d] * Wt[d];
    red[tid] = s; __syncthreads();
    for (int o = 128; o; o >>= 1){ if (tid < o) red[tid] += red[tid+o]; __syncthreads(); }
    if (tid == 0) g_temp[b] = 1.0f/(1.0f + expf(-(red[0] + bt[0]))) + 0.5f;
}

// ---------------- fp16 tensor-core GEMM: C(fp16) = A(fp16) @ W(fp16) + bias(fp32) ----------------
// BM=128, BN=128, BK=32, 256 threads, 8 warps (2M x 4N), warp tile 64x32
__global__ __launch_bounds__(256) void hgemm_bias(const __half* __restrict__ A,
                                                  const __half* __restrict__ Bw,
                                                  const float* __restrict__ bias,
                                                  __half* __restrict__ C,
                                                  int M, int N, int K){
    __shared__ __half As[2][128*SA];
    __shared__ __half Bs[2][32*SBP];
    const int tid = threadIdx.x, lane = tid & 31, wid = tid >> 5;
    const int m0 = blockIdx.y*128, n0 = blockIdx.x*128;
    const int wm = (wid & 1)*64, wn = (wid >> 1)*32;
    const int KT = K >> 5;
    float acc[4][4][4] = {};

    const int ar = tid >> 2, ac = (tid & 3) << 3;   // A: row (+64), col8
    const int br = tid >> 4, bc = (tid & 15) << 3;  // B: row (+16), col8

    #pragma unroll
    for (int c = 0; c < 2; ++c){
        *(float4*)&As[0][(ar+c*64)*SA + ac] =
            *(const float4*)(A + (size_t)(m0+ar+c*64)*K + ac);
        *(float4*)&Bs[0][(br+c*16)*SBP + bc] =
            *(const float4*)(Bw + (size_t)(br+c*16)*N + n0 + bc);
    }
    __syncthreads();

    for (int kt = 0; kt < KT; ++kt){
        const int cur = kt & 1;
        float4 ra[2], rb[2];
        const bool nxt = (kt+1 < KT);
        if (nxt){
            int k0 = (kt+1) << 5;
            #pragma unroll
            for (int c = 0; c < 2; ++c){
                ra[c] = *(const float4*)(A + (size_t)(m0+ar+c*64)*K + k0 + ac);
                rb[c] = *(const float4*)(Bw + (size_t)(k0+br+c*16)*N + n0 + bc);
            }
        }
        #pragma unroll
        for (int ks = 0; ks < 2; ++ks){
            unsigned af[4][4], bf[2][4];
            #pragma unroll
            for (int mt = 0; mt < 4; ++mt)
                ldsm4(af[mt], &As[cur][(wm+mt*16+(lane&15))*SA + ks*16 + (lane>>4)*8]);
            #pragma unroll
            for (int g = 0; g < 2; ++g)
                ldsm4t(bf[g], &Bs[cur][(ks*16+(lane&15))*SBP + wn + g*16 + (lane>>4)*8]);
            #pragma unroll
            for (int mt = 0; mt < 4; ++mt)
                #pragma unroll
                for (int g = 0; g < 2; ++g){
                    mma_f16(acc[mt][2*g],   af[mt], bf[g][0], bf[g][1]);
                    mma_f16(acc[mt][2*g+1], af[mt], bf[g][2], bf[g][3]);
                }
        }
        if (nxt){
            #pragma unroll
            for (int c = 0; c < 2; ++c){
                *(float4*)&As[cur^1][(ar+c*64)*SA + ac] = ra[c];
                *(float4*)&Bs[cur^1][(br+c*16)*SBP + bc] = rb[c];
            }
        }
        __syncthreads();
    }

    #pragma unroll
    for (int mt = 0; mt < 4; ++mt){
        int r = m0 + wm + mt*16 + (lane >> 2);
        #pragma unroll
        for (int nt = 0; nt < 4; ++nt){
            int c = n0 + wn + nt*8 + (lane & 3)*2;
            float b0 = bias[c], b1 = bias[c+1];
            *(__half2*)&C[(size_t)r*N + c] =
                __floats2half2_rn(acc[mt][nt][0]+b0, acc[mt][nt][1]+b1);
            *(__half2*)&C[(size_t)(r+8)*N + c] =
                __floats2half2_rn(acc[mt][nt][2]+b0, acc[mt][nt][3]+b1);
        }
    }
}

// ---------------- head split + L2 normalize (q,k) + v relayout (fp16) ----------------
__global__ __launch_bounds__(256) void norm_split(){
    int gw   = (blockIdx.x*256 + threadIdx.x) >> 5;   // one warp per (bh,s)
    int lane = threadIdx.x & 31;
    int s  = gw & (S_-1);
    int bh = gw >> 11;
    int h  = bh & (H_-1), b = bh >> 4;
    size_t src = ((size_t)(b*S_+s))*D_ + h*DH_ + lane*2;
    size_t dst = (size_t)gw * DH_ + lane*2;

    float2 qv = __half22float2(*(const __half2*)(g_qh + src));
    float ss = qv.x*qv.x + qv.y*qv.y;
    #pragma unroll
    for (int o = 16; o; o >>= 1) ss += __shfl_xor_sync(0xFFFFFFFFu, ss, o);
    float inv = 1.0f / fmaxf(sqrtf(ss), 1e-12f);
    *(__half2*)(g_qnh + dst) = __floats2half2_rn(qv.x*inv, qv.y*inv);

    float2 kv = __half22float2(*(const __half2*)(g_kh + src));
    ss = kv.x*kv.x + kv.y*kv.y;
    #pragma unroll
    for (int o = 16; o; o >>= 1) ss += __shfl_xor_sync(0xFFFFFFFFu, ss, o);
    inv = 1.0f / fmaxf(sqrtf(ss), 1e-12f);
    *(__half2*)(g_knh + dst) = __floats2half2_rn(kv.x*inv, kv.y*inv);

    *(__half2*)(g_vhh + dst) = *(const __half2*)(g_vh16 + src);
}

// ---------------- scores[z] = Qn[bh0+z] @ Kn[bh0+z]^T / temp  (fp16 mma, fp32 out) ----------------
__global__ __launch_bounds__(256) void scores_mma(int bh0){
    const int z = blockIdx.z, bh = bh0 + z, b = bh >> 4;
    const __half* Q  = g_qnh + (size_t)bh*S_*DH_;
    const __half* Kn = g_knh + (size_t)bh*S_*DH_;
    __shared__ __half As[2][128*SA];
    __shared__ __half Bs[2][128*SA];
    const int tid = threadIdx.x, lane = tid & 31, wid = tid >> 5;
    const int m0 = blockIdx.y*128, n0 = blockIdx.x*128;
    const int wm = (wid & 1)*64, wn = (wid >> 1)*32;
    float acc[4][4][4] = {};

    const int ar = tid >> 2, ac = (tid & 3) << 3;

    #pragma unroll
    for (int c = 0; c < 2; ++c){
        *(float4*)&As[0][(ar+c*64)*SA + ac] =
            *(const float4*)(Q + (size_t)(m0+ar+c*64)*DH_ + ac);
        *(float4*)&Bs[0][(ar+c*64)*SA + ac] =
            *(const float4*)(Kn + (size_t)(n0+ar+c*64)*DH_ + ac);
    }
    __syncthreads();

    const int KT = DH_ >> 5;  // 2
    for (int kt = 0; kt < KT; ++kt){
        const int cur = kt & 1;
        float4 ra[2], rb[2];
        const bool nxt = (kt+1 < KT);
        if (nxt){
            int k0 = (kt+1) << 5;
            #pragma unroll
            for (int c = 0; c < 2; ++c){
                ra[c] = *(const float4*)(Q  + (size_t)(m0+ar+c*64)*DH_ + k0 + ac);
                rb[c] = *(const float4*)(Kn + (size_t)(n0+ar+c*64)*DH_ + k0 + ac);
            }
        }
        #pragma unroll
        for (int ks = 0; ks < 2; ++ks){
            unsigned af[4][4], bf[2][4];
            #pragma unroll
            for (int mt = 0; mt < 4; ++mt)
                ldsm4(af[mt], &As[cur][(wm+mt*16+(lane&15))*SA + ks*16 + (lane>>4)*8]);
            #pragma unroll
            for (int g = 0; g < 2; ++g)
                ldsm4(bf[g], &Bs[cur][(wn + g*16 + ((lane>>4)<<3) + (lane&7))*SA
                                      + ks*16 + ((lane>>3)&1)*8]);
            #pragma unroll
            for (int mt = 0; mt < 4; ++mt)
                #pragma unroll
                for (int g = 0; g < 2; ++g){
                    mma_f16(acc[mt][2*g],   af[mt], bf[g][0], bf[g][1]);
                    mma_f16(acc[mt][2*g+1], af[mt], bf[g][2], bf[g][3]);
                }
        }
        if (nxt){
            #pragma unroll
            for (int c = 0; c < 2; ++c){
                *(float4*)&As[cur^1][(ar+c*64)*SA + ac] = ra[c];
                *(float4*)&Bs[cur^1][(ar+c*64)*SA + ac] = rb[c];
            }
        }
        __syncthreads();
    }

    const float sc = 1.0f / g_temp[b];
    #pragma unroll
    for (int mt = 0; mt < 4; ++mt){
        int r = m0 + wm + mt*16 + (lane >> 2);
        #pragma unroll
        for (int nt = 0; nt < 4; ++nt){
            int c = n0 + wn + nt*8 + (lane & 3)*2;
            float2 o0 = make_float2(acc[mt][nt][0]*sc, acc[mt][nt][1]*sc);
            float2 o1 = make_float2(acc[mt][nt][2]*sc, acc[mt][nt][3]*sc);
            *(float2*)&g_scores[((size_t)z*S_ + r)*S_ + c]     = o0;
            *(float2*)&g_scores[((size_t)z*S_ + r + 8)*S_ + c] = o1;
        }
    }
}

// ---------------- exact top-512 radix-select + softmax -> fp16 weights (local group) ----------------
__global__ __launch_bounds__(256) void topk_softmax(){
    const size_t row = blockIdx.x;                   // 0 .. GH_*S_-1
    const float* sp = g_scores + row*(size_t)S_;
    __half* ap = g_attnh + row*(size_t)S_;
    __shared__ unsigned hist[256];
    __shared__ unsigned sufs[256];
    __shared__ unsigned wsum[8];
    __shared__ float fr[8];
    __shared__ unsigned s_bin, s_above;
    __shared__ float s_mx, s_sum;
    const int tid = threadIdx.x, lane = tid & 31, wid = tid >> 5;

    float v[8]; unsigned key[8];
    #pragma unroll
    for (int i = 0; i < 8; ++i){
        v[i] = sp[i*256 + tid];
        unsigned u = __float_as_uint(v[i]);
        key[i] = u ^ (((unsigned)((int)u >> 31)) | 0x80000000u);
    }

    unsigned prefix = 0, remaining = KK_;
    #pragma unroll
    for (int shift = 24; shift >= 0; shift -= 8){
        hist[tid] = 0; __syncthreads();
        unsigned pmask = (shift == 24) ? 0u : (0xFFFFFFFFu << (shift+8));
        #pragma unroll
        for (int i = 0; i < 8; ++i)
            if ((key[i] & pmask) == prefix) atomicAdd(&hist[(key[i] >> shift) & 255], 1u);
        __syncthreads();
        unsigned x = hist[255 - tid];
        #pragma unroll
        for (int o = 1; o < 32; o <<= 1){
            unsigned t = __shfl_up_sync(0xFFFFFFFFu, x, o);
            if (lane >= o) x += t;
        }
        if (lane == 31) wsum[wid] = x;
        __syncthreads();
        if (tid < 8){
            unsigned w = wsum[tid];
            #pragma unroll
            for (int o = 1; o < 8; o <<= 1){
                unsigned t = __shfl_up_sync(0xFFu, w, o);
                if (tid >= o) w += t;
            }
            wsum[tid] = w;
        }
        __syncthreads();
        unsigned suf = x + (wid ? wsum[wid-1] : 0u);
        sufs[255 - tid] = suf;
        __syncthreads();
        unsigned Sb  = sufs[tid];
        unsigned Sb1 = (tid < 255) ? sufs[tid+1] : 0u;
        if (Sb >= remaining && Sb1 < remaining){ s_bin = (unsigned)tid; s_above = Sb1; }
        __syncthreads();
        remaining -= s_above;
        prefix |= (s_bin << shift);
    }
    const unsigned T = prefix;

    float mx = -3.402823466e38f;
    #pragma unroll
    for (int i = 0; i < 8; ++i) mx = fmaxf(mx, v[i]);
    #pragma unroll
    for (int o = 16; o; o >>= 1) mx = fmaxf(mx, __shfl_xor_sync(0xFFFFFFFFu, mx, o));
    if (lane == 0) fr[wid] = mx;
    __syncthreads();
    if (tid == 0){
        float m = fr[0];
        #pragma unroll
        for (int j = 1; j < 8; ++j) m = fmaxf(m, fr[j]);
        s_mx = m;
    }
    __syncthreads();
    mx = s_mx;

    float e[8]; float ls = 0.f;
    #pragma unroll
    for (int i = 0; i < 8; ++i){
        e[i] = (key[i] >= T) ? expf(v[i] - mx) : 0.0f;
        ls += e[i];
    }
    #pragma unroll
    for (int o = 16; o; o >>= 1) ls += __shfl_xor_sync(0xFFFFFFFFu, ls, o);
    if (lane == 0) fr[wid] = ls;
    __syncthreads();
    if (tid == 0){
        float m = 0.f;
        #pragma unroll
        for (int j = 0; j < 8; ++j) m += fr[j];
        s_sum = m;
    }
    __syncthreads();
    const float inv = 1.0f / s_sum;
    #pragma unroll
    for (int i = 0; i < 8; ++i) ap[i*256 + tid] = __float2half(e[i]*inv);
}

// ---------------- O = attn @ V  (fp16 mma), BM=64, 8 warps (4M x 2N) ----------------
__global__ __launch_bounds__(256) void av_mma(int bh0){
    const int z = blockIdx.z, bh = bh0 + z;
    const int m0 = blockIdx.y*64;
    const __half* A = g_attnh + (size_t)z*S_*S_;
    const __half* V = g_vhh   + (size_t)bh*S_*DH_;
    __shared__ __half As[2][64*SA];
    __shared__ __half Bs[2][32*SBV];
    const int tid = threadIdx.x, lane = tid & 31, wid = tid >> 5;
    const int wm = (wid & 3)*16, wn = (wid >> 2)*32;
    float acc[4][4] = {};

    const int ar = tid >> 2, ac = (tid & 3) << 3;   // 64 rows x 4 float4
    const int br = tid >> 3, bc = (tid & 7) << 3;   // 32 rows x 8 float4

    *(float4*)&As[0][ar*SA + ac] = *(const float4*)(A + (size_t)(m0+ar)*S_ + ac);
    *(float4*)&Bs[0][br*SBV + bc] = *(const float4*)(V + (size_t)br*DH_ + bc);
    __syncthreads();

    const int KT = S_ >> 5;  // 64
    for (int kt = 0; kt < KT; ++kt){
        const int cur = kt & 1;
        float4 ra, rb;
        const bool nxt = (kt+1 < KT);
        if (nxt){
            int k0 = (kt+1) << 5;
            ra = *(const float4*)(A + (size_t)(m0+ar)*S_ + k0 + ac);
            rb = *(const float4*)(V + (size_t)(k0+br)*DH_ + bc);
        }
        #pragma unroll
        for (int ks = 0; ks < 2; ++ks){
            unsigned af[4], bf[2][4];
            ldsm4(af, &As[cur][(wm+(lane&15))*SA + ks*16 + (lane>>4)*8]);
            #pragma unroll
            for (int g = 0; g < 2; ++g)
                ldsm4t(bf[g], &Bs[cur][(ks*16+(lane&15))*SBV + wn + g*16 + (lane>>4)*8]);
            #pragma unroll
            for (int g = 0; g < 2; ++g){
                mma_f16(acc[2*g],   af, bf[g][0], bf[g][1]);
                mma_f16(acc[2*g+1], af, bf[g][2], bf[g][3]);
            }
        }
        if (nxt){
            *(float4*)&As[cur^1][ar*SA + ac] = ra;
            *(float4*)&Bs[cur^1][br*SBV + bc] = rb;
        }
        __syncthreads();
    }

    const int bb = bh >> 4, h = bh & (H_-1);
    int s_idx = m0 + wm + (lane >> 2);
    size_t grow0 = (size_t)(bb*S_ + s_idx)*D_;
    size_t grow1 = (size_t)(bb*S_ + s_idx + 8)*D_;
    #pragma unroll
    for (int nt = 0; nt < 4; ++nt){
        int c = h*DH_ + wn + nt*8 + (lane & 3)*2;
        *(__half2*)&g_obsdh[grow0 + c] = __floats2half2_rn(acc[nt][0], acc[nt][1]);
        *(__half2*)&g_obsdh[grow1 + c] = __floats2half2_rn(acc[nt][2], acc[nt][3]);
    }
}

// ---------------- highway gating ----------------
__global__ __launch_bounds__(256) void finalize_kernel(const float* __restrict__ x,
                                                       float* __restrict__ out){
    int i = blockIdx.x*256 + threadIdx.x;    // over M*D/2 pairs
    float2 xv = reinterpret_cast<const float2*>(x)[i];
    float2 gv = __half22float2(reinterpret_cast<const __half2*>(g_gateh)[i]);
    float2 ov = __half22float2(reinterpret_cast<const __half2*>(g_out2h)[i]);
    float2 r;
    float g;
    g = 1.0f/(1.0f+expf(-gv.x)); r.x = g*ov.x + (1.0f-g)*xv.x;
    g = 1.0f/(1.0f+expf(-gv.y)); r.y = g*ov.y + (1.0f-g)*xv.y;
    reinterpret_cast<float2*>(out)[i] = r;
}

// ---------------- launch ----------------
extern "C" void kernel_launch(void* const* d_in, const int* in_sizes, int n_in,
                              void* d_out, int out_size){
    (void)in_sizes; (void)n_in; (void)out_size;
    const float* x  = (const float*)d_in[0];
    const float* Wq = (const float*)d_in[1];  const float* bq = (const float*)d_in[2];
    const float* Wk = (const float*)d_in[3];  const float* bk = (const float*)d_in[4];
    const float* Wv = (const float*)d_in[5];  const float* bv = (const float*)d_in[6];
    const float* Wo = (const float*)d_in[7];  const float* bo = (const float*)d_in[8];
    const float* Wt = (const float*)d_in[9];  const float* bt = (const float*)d_in[10];
    const float* Wg = (const float*)d_in[11]; const float* bg = (const float*)d_in[12];
    float* out = (float*)d_out;

    __half *xh,*Wqh,*Wkh,*Wvh,*Wgh,*Woh,*qh,*kh,*vh,*gh,*obsdh,*out2h;
    cudaGetSymbolAddress((void**)&xh,    g_xh);
    cudaGetSymbolAddress((void**)&Wqh,   g_Wqh);
    cudaGetSymbolAddress((void**)&Wkh,   g_Wkh);
    cudaGetSymbolAddress((void**)&Wvh,   g_Wvh);
    cudaGetSymbolAddress((void**)&Wgh,   g_Wgh);
    cudaGetSymbolAddress((void**)&Woh,   g_Woh);
    cudaGetSymbolAddress((void**)&qh,    g_qh);
    cudaGetSymbolAddress((void**)&kh,    g_kh);
    cudaGetSymbolAddress((void**)&vh,    g_vh16);
    cudaGetSymbolAddress((void**)&gh,    g_gateh);
    cudaGetSymbolAddress((void**)&obsdh, g_obsdh);
    cudaGetSymbolAddress((void**)&out2h, g_out2h);

    // conversions needed for the first GEMM (launches 1-5), then hgemm as launch 6
    // so ncu (-s 5 -c 1) profiles a tensor-core GEMM.
    f2h_kernel<<<(M_*D_)/1024, 256>>>(x,  xh);
    f2h_kernel<<<(D_*D_)/1024, 256>>>(Wq, Wqh);
    f2h_kernel<<<(D_*D_)/1024, 256>>>(Wk, Wkh);
    f2h_kernel<<<(D_*D_)/1024, 256>>>(Wv, Wvh);
    f2h_kernel<<<(D_*D_)/1024, 256>>>(Wg, Wgh);

    dim3 gg(D_/128, M_/128);   // (8, 32)
    hgemm_bias<<<gg, 256>>>(xh, Wqh, bq, qh, M_, D_, D_);   // <-- profiled
    hgemm_bias<<<gg, 256>>>(xh, Wkh, bk, kh, M_, D_, D_);
    hgemm_bias<<<gg, 256>>>(xh, Wvh, bv, vh, M_, D_, D_);
    hgemm_bias<<<gg, 256>>>(xh, Wgh, bg, gh, M_, D_, D_);

    f2h_kernel<<<(D_*D_)/1024, 256>>>(Wo, Woh);

    // temperature path (fp32)
    mean_stage1<<<B_*MCH_, 256>>>(x);
    mean_stage2<<<(B_*D_)/256, 256>>>();
    temp_kernel<<<B_, 256>>>(Wt, bt);

    // normalize + head relayout
    norm_split<<<(BH_*S_*32)/256, 256>>>();

    // L2-resident head groups: scores -> topk -> av reuse the same 96MB window
    for (int grp = 0; grp < BH_/GH_; ++grp){
        int bh0 = grp*GH_;
        scores_mma<<<dim3(S_/128, S_/128, GH_), 256>>>(bh0);
        topk_softmax<<<GH_*S_, 256>>>();
        av_mma<<<dim3(1, S_/64, GH_), 256>>>(bh0);
    }

    // output projection + highway gate
    hgemm_bias<<<gg, 256>>>(obsdh, Woh, bo, out2h, M_, D_, D_);
    finalize_kernel<<<(M_*D_/2)/256, 256>>>(x, out);
}

// round 4
// speedup vs baseline: 1.0125x; 1.0125x over previous
#include <cuda_runtime.h>
#include <cuda_fp16.h>
#include <math.h>

#define B_   2
#define S_   2048
#define D_   1024
#define H_   16
#define DH_  64
#define M_   (B_*S_)          // 4096 tokens
#define BH_  (B_*H_)          // 32
#define KK_  512              // top-k
#define MCH_ 16               // mean chunks

#define SA   40               // smem row stride (halves) for 32-col k-tiles (hgemm A)
#define SBP  136              // smem row stride for 128-col B tiles (hgemm B)

// fused-attention smem geometry
#define SCST 2052             // score row stride in floats (16 rows)
#define KVST 72               // K/V chunk row stride in halves

// ---------------- scratch (static device memory; no allocations) ----------------
__device__ __half g_xh[M_*D_];
__device__ __half g_Wcat[D_*4*D_];     // packed [1024][4096] : Wq|Wk|Wv|Wg
__device__ float  g_bcat[4*D_];
__device__ __half g_Woh[D_*D_];
__device__ __half g_qkvgh[(size_t)M_*4*D_];  // [4096][4096] : q|k|v|gate
__device__ __half g_qnh[M_*D_];     // [BH][S][DH]
__device__ __half g_knh[M_*D_];     // [BH][S][DH]
__device__ __half g_vhh[M_*D_];     // [BH][S][DH]
__device__ __half g_obsdh[M_*D_];   // attention output in [B,S,D]
__device__ __half g_out2h[M_*D_];   // after Wo
__device__ float  g_xpart[MCH_*B_*D_];
__device__ float  g_xmean[B_*D_];
__device__ float  g_temp[B_];

// ---------------- mma / ldmatrix helpers ----------------
__device__ __forceinline__ void mma_f16(float* d, const unsigned* a, unsigned b0, unsigned b1){
    asm volatile("mma.sync.aligned.m16n8k16.row.col.f32.f16.f16.f32 "
        "{%0,%1,%2,%3}, {%4,%5,%6,%7}, {%8,%9}, {%0,%1,%2,%3};\n"
        : "+f"(d[0]),"+f"(d[1]),"+f"(d[2]),"+f"(d[3])
        : "r"(a[0]),"r"(a[1]),"r"(a[2]),"r"(a[3]), "r"(b0),"r"(b1));
}
__device__ __forceinline__ void ldsm4(unsigned* r, const __half* p){
    unsigned addr = (unsigned)__cvta_generic_to_shared(p);
    asm volatile("ldmatrix.sync.aligned.m8n8.x4.shared.b16 {%0,%1,%2,%3}, [%4];\n"
        :"=r"(r[0]),"=r"(r[1]),"=r"(r[2]),"=r"(r[3]) : "r"(addr));
}
__device__ __forceinline__ void ldsm4t(unsigned* r, const __half* p){
    unsigned addr = (unsigned)__cvta_generic_to_shared(p);
    asm volatile("ldmatrix.sync.aligned.m8n8.x4.trans.shared.b16 {%0,%1,%2,%3}, [%4];\n"
        :"=r"(r[0]),"=r"(r[1]),"=r"(r[2]),"=r"(r[3]) : "r"(addr));
}

// ---------------- fp32 -> fp16 conversion ----------------
__global__ __launch_bounds__(256) void f2h_kernel(const float* __restrict__ in,
                                                  __half* __restrict__ out){
    int i = blockIdx.x*256 + threadIdx.x;
    float4 v = reinterpret_cast<const float4*>(in)[i];
    reinterpret_cast<__half2*>(out)[2*i]   = __floats2half2_rn(v.x, v.y);
    reinterpret_cast<__half2*>(out)[2*i+1] = __floats2half2_rn(v.z, v.w);
}

// pack a 1024x1024 fp32 weight into column block col0 of [1024][4096] halves
__global__ __launch_bounds__(256) void f2h_pack(const float* __restrict__ in,
                                                __half* __restrict__ out, int col0){
    int i = blockIdx.x*256 + threadIdx.x;      // over 1024*1024/4 float4s
    int row = i >> 8, c4 = (i & 255) * 4;
    float4 v = reinterpret_cast<const float4*>(in)[i];
    __half* o = out + (size_t)row*4096 + col0 + c4;
    *(__half2*)&o[0] = __floats2half2_rn(v.x, v.y);
    *(__half2*)&o[2] = __floats2half2_rn(v.z, v.w);
}

__global__ __launch_bounds__(256) void pack_bias(const float* __restrict__ bq,
                                                 const float* __restrict__ bk,
                                                 const float* __restrict__ bv,
                                                 const float* __restrict__ bg){
    int idx = blockIdx.x*256 + threadIdx.x;    // 4096
    int seg = idx >> 10, j = idx & 1023;
    float v = (seg==0) ? bq[j] : (seg==1) ? bk[j] : (seg==2) ? bv[j] : bg[j];
    g_bcat[idx] = v;
}

// ---------------- mean over sequence + temperature ----------------
__global__ __launch_bounds__(256) void mean_stage1(const float* __restrict__ x){
    int b  = blockIdx.x / MCH_;
    int ch = blockIdx.x % MCH_;
    int s0 = ch * (S_/MCH_);
    int tid = threadIdx.x;
    float acc[4] = {0.f,0.f,0.f,0.f};
    for (int s = s0; s < s0 + S_/MCH_; ++s){
        const float* xp = x + ((size_t)(b*S_+s))*D_;
        #pragma unroll
        for (int j = 0; j < 4; ++j) acc[j] += xp[tid + j*256];
    }
    #pragma unroll
    for (int j = 0; j < 4; ++j) g_xpart[((size_t)ch*B_ + b)*D_ + tid + j*256] = acc[j];
}

__global__ __launch_bounds__(256) void mean_stage2(){
    int idx = blockIdx.x*256 + threadIdx.x;
    int b = idx / D_, d = idx % D_;
    float s = 0.f;
    #pragma unroll
    for (int ch = 0; ch < MCH_; ++ch) s += g_xpart[((size_t)ch*B_ + b)*D_ + d];
    g_xmean[idx] = s * (1.0f/S_);
}

__global__ __launch_bounds__(256) void temp_kernel(const float* __restrict__ Wt,
                                                   const float* __restrict__ bt){
    __shared__ float red[256];
    int b = blockIdx.x, tid = threadIdx.x;
    float s = 0.f;
    for (int d = tid; d < D_; d += 256) s += g_xmean[b*D_ + d] * Wt[d];
    red[tid] = s; __syncthreads();
    for (int o = 128; o; o >>= 1){ if (tid < o) red[tid] += red[tid+o]; __syncthreads(); }
    if (tid == 0) g_temp[b] = 1.0f/(1.0f + expf(-(red[0] + bt[0]))) + 0.5f;
}

// ---------------- fp16 tensor-core GEMM: C(fp16) = A @ W + bias ----------------
__global__ __launch_bounds__(256) void hgemm_bias(const __half* __restrict__ A,
                                                  const __half* __restrict__ Bw,
                                                  const float* __restrict__ bias,
                                                  __half* __restrict__ C,
                                                  int M, int N, int K){
    __shared__ __half As[2][128*SA];
    __shared__ __half Bs[2][32*SBP];
    const int tid = threadIdx.x, lane = tid & 31, wid = tid >> 5;
    const int m0 = blockIdx.y*128, n0 = blockIdx.x*128;
    const int wm = (wid & 1)*64, wn = (wid >> 1)*32;
    const int KT = K >> 5;
    float acc[4][4][4] = {};

    const int ar = tid >> 2, ac = (tid & 3) << 3;
    const int br = tid >> 4, bc = (tid & 15) << 3;

    #pragma unroll
    for (int c = 0; c < 2; ++c){
        *(float4*)&As[0][(ar+c*64)*SA + ac] =
            *(const float4*)(A + (size_t)(m0+ar+c*64)*K + ac);
        *(float4*)&Bs[0][(br+c*16)*SBP + bc] =
            *(const float4*)(Bw + (size_t)(br+c*16)*N + n0 + bc);
    }
    __syncthreads();

    for (int kt = 0; kt < KT; ++kt){
        const int cur = kt & 1;
        float4 ra[2], rb[2];
        const bool nxt = (kt+1 < KT);
        if (nxt){
            int k0 = (kt+1) << 5;
            #pragma unroll
            for (int c = 0; c < 2; ++c){
                ra[c] = *(const float4*)(A + (size_t)(m0+ar+c*64)*K + k0 + ac);
                rb[c] = *(const float4*)(Bw + (size_t)(k0+br+c*16)*N + n0 + bc);
            }
        }
        #pragma unroll
        for (int ks = 0; ks < 2; ++ks){
            unsigned af[4][4], bf[2][4];
            #pragma unroll
            for (int mt = 0; mt < 4; ++mt)
                ldsm4(af[mt], &As[cur][(wm+mt*16+(lane&15))*SA + ks*16 + (lane>>4)*8]);
            #pragma unroll
            for (int g = 0; g < 2; ++g)
                ldsm4t(bf[g], &Bs[cur][(ks*16+(lane&15))*SBP + wn + g*16 + (lane>>4)*8]);
            #pragma unroll
            for (int mt = 0; mt < 4; ++mt)
                #pragma unroll
                for (int g = 0; g < 2; ++g){
                    mma_f16(acc[mt][2*g],   af[mt], bf[g][0], bf[g][1]);
                    mma_f16(acc[mt][2*g+1], af[mt], bf[g][2], bf[g][3]);
                }
        }
        if (nxt){
            #pragma unroll
            for (int c = 0; c < 2; ++c){
                *(float4*)&As[cur^1][(ar+c*64)*SA + ac] = ra[c];
                *(float4*)&Bs[cur^1][(br+c*16)*SBP + bc] = rb[c];
            }
        }
        __syncthreads();
    }

    #pragma unroll
    for (int mt = 0; mt < 4; ++mt){
        int r = m0 + wm + mt*16 + (lane >> 2);
        #pragma unroll
        for (int nt = 0; nt < 4; ++nt){
            int c = n0 + wn + nt*8 + (lane & 3)*2;
            float b0 = bias[c], b1 = bias[c+1];
            *(__half2*)&C[(size_t)r*N + c] =
                __floats2half2_rn(acc[mt][nt][0]+b0, acc[mt][nt][1]+b1);
            *(__half2*)&C[(size_t)(r+8)*N + c] =
                __floats2half2_rn(acc[mt][nt][2]+b0, acc[mt][nt][3]+b1);
        }
    }
}

// ---------------- head split + L2 normalize (q,k) + v relayout (from qkvg) ----------------
__global__ __launch_bounds__(256) void norm_split(){
    int gw   = (blockIdx.x*256 + threadIdx.x) >> 5;   // one warp per (bh,s)
    int lane = threadIdx.x & 31;
    int s  = gw & (S_-1);
    int bh = gw >> 11;
    int h  = bh & (H_-1), b = bh >> 4;
    size_t row = (size_t)(b*S_+s)*4096;
    int hc = h*DH_ + lane*2;
    size_t dst = (size_t)gw * DH_ + lane*2;

    float2 qv = __half22float2(*(const __half2*)(g_qkvgh + row + hc));
    float ss = qv.x*qv.x + qv.y*qv.y;
    #pragma unroll
    for (int o = 16; o; o >>= 1) ss += __shfl_xor_sync(0xFFFFFFFFu, ss, o);
    float inv = 1.0f / fmaxf(sqrtf(ss), 1e-12f);
    *(__half2*)(g_qnh + dst) = __floats2half2_rn(qv.x*inv, qv.y*inv);

    float2 kv = __half22float2(*(const __half2*)(g_qkvgh + row + 1024 + hc));
    ss = kv.x*kv.x + kv.y*kv.y;
    #pragma unroll
    for (int o = 16; o; o >>= 1) ss += __shfl_xor_sync(0xFFFFFFFFu, ss, o);
    inv = 1.0f / fmaxf(sqrtf(ss), 1e-12f);
    *(__half2*)(g_knh + dst) = __floats2half2_rn(kv.x*inv, kv.y*inv);

    *(__half2*)(g_vhh + dst) = *(const __half2*)(g_qkvgh + row + 2048 + hc);
}

// ---------------- fused attention: scores + exact top-512 + softmax + attn@V ----------------
// grid (128 row-tiles, 32 heads), 512 threads (16 warps), 1 block/SM.
// smem: fp32 scores 16x2052 | Q 16x72 | KV chunk 256x72 | hist 16x256 | red 3x4x16x16
#define OFF_Q    131328
#define OFF_KV   133632
#define OFF_HIST 170496
#define OFF_RED  186880
#define SMEM_ATTN 199168

__global__ __launch_bounds__(512, 1) void fused_attn(){
    extern __shared__ char smem[];
    float*    sc   = (float*)smem;
    __half*   Qs   = (__half*)(smem + OFF_Q);
    __half*   KV   = (__half*)(smem + OFF_KV);
    unsigned* hist = (unsigned*)(smem + OFF_HIST);
    float*    red  = (float*)(smem + OFF_RED);

    const int tid = threadIdx.x, lane = tid & 31, w = tid >> 5;   // 16 warps
    const int m0 = blockIdx.x * 16;
    const int bh = blockIdx.y, b = bh >> 4, h = bh & (H_-1);
    const float invt = 1.0f / g_temp[b];

    const __half* Qg = g_qnh + (size_t)bh*S_*DH_;
    const __half* Kg = g_knh + (size_t)bh*S_*DH_;
    const __half* Vg = g_vhh + (size_t)bh*S_*DH_;

    // ---- load Q tile (16 x 64) ----
    if (tid < 128){
        int row = tid >> 3, c8 = (tid & 7) * 8;
        *(float4*)&Qs[row*KVST + c8] = *(const float4*)(Qg + (size_t)(m0+row)*DH_ + c8);
    }
    __syncthreads();

    // Q fragments (reused across all chunks)
    unsigned af[4][4];
    #pragma unroll
    for (int ks = 0; ks < 4; ++ks)
        ldsm4(af[ks], &Qs[(lane&15)*KVST + ks*16 + (lane>>4)*8]);

    // ---- phase 1: scores (16 x 2048), 8 chunks of 256 keys ----
    for (int c = 0; c < 8; ++c){
        __syncthreads();   // KV buffer safe to overwrite
        #pragma unroll
        for (int j = 0; j < 4; ++j){
            int idx = j*512 + tid;            // 2048 float4s
            int row = idx >> 3, c8 = (idx & 7) * 8;
            *(float4*)&KV[row*KVST + c8] =
                *(const float4*)(Kg + (size_t)(c*256+row)*DH_ + c8);
        }
        __syncthreads();

        float acc[2][4] = {};
        #pragma unroll
        for (int ks = 0; ks < 4; ++ks){
            unsigned bf[4];
            ldsm4(bf, &KV[(w*16 + ((lane>>4)<<3) + (lane&7))*KVST
                          + ks*16 + ((lane>>3)&1)*8]);
            mma_f16(acc[0], af[ks], bf[0], bf[1]);
            mma_f16(acc[1], af[ks], bf[2], bf[3]);
        }
        int r0 = lane >> 2;
        #pragma unroll
        for (int nt = 0; nt < 2; ++nt){
            int gcol = c*256 + w*16 + nt*8 + (lane & 3)*2;
            *(float2*)&sc[r0*SCST + gcol]     = make_float2(acc[nt][0]*invt, acc[nt][1]*invt);
            *(float2*)&sc[(r0+8)*SCST + gcol] = make_float2(acc[nt][2]*invt, acc[nt][3]*invt);
        }
    }
    __syncthreads();   // all scores visible

    // ---- phase 2: warp-local exact top-512 radix select + softmax (row = w) ----
    {
        float* srow = sc + w*SCST;
        __half* hrow = (__half*)(sc) + w*(SCST*2);
        unsigned* hb = hist + w*256;

        unsigned prefix = 0, remaining = KK_;
        float mx = -3.402823466e38f;
        #pragma unroll
        for (int pass = 0; pass < 4; ++pass){
            const int shift = 24 - pass*8;
            #pragma unroll
            for (int j = 0; j < 8; ++j) hb[lane*8 + j] = 0;
            __syncwarp();
            unsigned pmask = (pass == 0) ? 0u : (0xFFFFFFFFu << (shift+8));
            for (int i = 0; i < 64; ++i){
                float v = srow[i*32 + lane];
                if (pass == 0) mx = fmaxf(mx, v);
                unsigned u = __float_as_uint(v);
                unsigned key = u ^ (((unsigned)((int)u >> 31)) | 0x80000000u);
                if ((key & pmask) == prefix)
                    atomicAdd(&hb[(key >> shift) & 255], 1u);
            }
            __syncwarp();
            unsigned hv[8], suf[8];
            #pragma unroll
            for (int j = 0; j < 8; ++j) hv[j] = hb[lane*8 + j];
            suf[7] = hv[7];
            #pragma unroll
            for (int j = 6; j >= 0; --j) suf[j] = suf[j+1] + hv[j];
            unsigned x = suf[0];
            #pragma unroll
            for (int o = 1; o < 32; o <<= 1){
                unsigned t = __shfl_down_sync(0xFFFFFFFFu, x, o);
                if (lane + o < 32) x += t;
            }
            unsigned tnx = __shfl_down_sync(0xFFFFFFFFu, x, 1);
            unsigned ex = (lane == 31) ? 0u : tnx;
            unsigned pick = 0xFFFFFFFFu;
            #pragma unroll
            for (int j = 0; j < 8; ++j){
                unsigned sb  = ex + suf[j];
                unsigned sb1 = (j < 7) ? (ex + suf[j+1]) : ex;
                if (sb >= remaining && sb1 < remaining)
                    pick = ((unsigned)(lane*8 + j) << 16) | sb1;
            }
            pick = __reduce_min_sync(0xFFFFFFFFu, pick);
            unsigned bin = pick >> 16, above = pick & 0xFFFFu;
            remaining -= above;
            prefix |= bin << shift;
        }
        const unsigned T = prefix;
        #pragma unroll
        for (int o = 16; o; o >>= 1) mx = fmaxf(mx, __shfl_xor_sync(0xFFFFFFFFu, mx, o));

        // sum pass
        float ls = 0.f;
        for (int i = 0; i < 64; ++i){
            float v = srow[i*32 + lane];
            unsigned u = __float_as_uint(v);
            unsigned key = u ^ (((unsigned)((int)u >> 31)) | 0x80000000u);
            if (key >= T) ls += expf(v - mx);
        }
        #pragma unroll
        for (int o = 16; o; o >>= 1) ls += __shfl_xor_sync(0xFFFFFFFFu, ls, o);
        const float inv = 1.0f / ls;

        // write fp16 weights in place (2 hazard-safe chunks of 1024)
        #pragma unroll
        for (int ch = 0; ch < 2; ++ch){
            float wv[32];
            #pragma unroll
            for (int i = 0; i < 32; ++i){
                int idx = ch*1024 + i*32 + lane;
                float v = srow[idx];
                unsigned u = __float_as_uint(v);
                unsigned key = u ^ (((unsigned)((int)u >> 31)) | 0x80000000u);
                wv[i] = (key >= T) ? expf(v - mx)*inv : 0.0f;
            }
            __syncwarp();
            #pragma unroll
            for (int i = 0; i < 32; ++i)
                hrow[ch*1024 + i*32 + lane] = __float2half(wv[i]);
            __syncwarp();
        }
    }
    __syncthreads();   // all weights ready

    // ---- phase 3: out(16x64) = W(16x2048) @ V(2048x64) ----
    const int kw = w >> 2, nw = w & 3;          // K-quarter, N 16-col slice
    const __half* Wsh = (__half*)(sc);
    float acc[2][4] = {};
    for (int c = 0; c < 8; ++c){
        __syncthreads();
        #pragma unroll
        for (int j = 0; j < 4; ++j){
            int idx = j*512 + tid;
            int row = idx >> 3, c8 = (idx & 7) * 8;
            *(float4*)&KV[row*KVST + c8] =
                *(const float4*)(Vg + (size_t)(c*256+row)*DH_ + c8);
        }
        __syncthreads();
        #pragma unroll
        for (int ks = 0; ks < 4; ++ks){
            int kr = kw*64 + ks*16;
            unsigned a2[4], bf[4];
            ldsm4(a2, &Wsh[(lane&15)*(SCST*2) + c*256 + kr + (lane>>4)*8]);
            ldsm4t(bf, &KV[(kr + (lane&15))*KVST + nw*16 + (lane>>4)*8]);
            mma_f16(acc[0], a2, bf[0], bf[1]);
            mma_f16(acc[1], a2, bf[2], bf[3]);
        }
    }

    // reduce across kw and write out
    int r0 = lane >> 2;
    if (kw > 0){
        float* rb = red + ((kw-1)*4 + nw)*256;
        #pragma unroll
        for (int nt = 0; nt < 2; ++nt){
            int col = nt*8 + (lane & 3)*2;
            *(float2*)&rb[r0*16 + col]     = make_float2(acc[nt][0], acc[nt][1]);
            *(float2*)&rb[(r0+8)*16 + col] = make_float2(acc[nt][2], acc[nt][3]);
        }
    }
    __syncthreads();
    if (kw == 0){
        #pragma unroll
        for (int p = 0; p < 3; ++p){
            float* rb = red + (p*4 + nw)*256;
            #pragma unroll
            for (int nt = 0; nt < 2; ++nt){
                int col = nt*8 + (lane & 3)*2;
                float2 v0 = *(float2*)&rb[r0*16 + col];
                float2 v1 = *(float2*)&rb[(r0+8)*16 + col];
                acc[nt][0] += v0.x; acc[nt][1] += v0.y;
                acc[nt][2] += v1.x; acc[nt][3] += v1.y;
            }
        }
        size_t g0 = (size_t)(b*S_ + m0 + r0)*D_;
        size_t g1 = (size_t)(b*S_ + m0 + r0 + 8)*D_;
        #pragma unroll
        for (int nt = 0; nt < 2; ++nt){
            int gc = h*DH_ + nw*16 + nt*8 + (lane & 3)*2;
            *(__half2*)&g_obsdh[g0 + gc] = __floats2half2_rn(acc[nt][0], acc[nt][1]);
            *(__half2*)&g_obsdh[g1 + gc] = __floats2half2_rn(acc[nt][2], acc[nt][3]);
        }
    }
}

// ---------------- highway gating ----------------
__global__ __launch_bounds__(256) void finalize_kernel(const float* __restrict__ x,
                                                       float* __restrict__ out){
    int i = blockIdx.x*256 + threadIdx.x;    // over M*D/2 pairs
    int p = 2*i;
    int r = p >> 10, cb = p & 1023;
    float2 xv = reinterpret_cast<const float2*>(x)[i];
    float2 gv = __half22float2(*(const __half2*)&g_qkvgh[(size_t)r*4096 + 3072 + cb]);
    float2 ov = __half22float2(reinterpret_cast<const __half2*>(g_out2h)[i]);
    float2 rr;
    float g;
    g = 1.0f/(1.0f+expf(-gv.x)); rr.x = g*ov.x + (1.0f-g)*xv.x;
    g = 1.0f/(1.0f+expf(-gv.y)); rr.y = g*ov.y + (1.0f-g)*xv.y;
    reinterpret_cast<float2*>(out)[i] = rr;
}

// ---------------- launch ----------------
extern "C" void kernel_launch(void* const* d_in, const int* in_sizes, int n_in,
                              void* d_out, int out_size){
    (void)in_sizes; (void)n_in; (void)out_size;
    const float* x  = (const float*)d_in[0];
    const float* Wq = (const float*)d_in[1];  const float* bq = (const float*)d_in[2];
    const float* Wk = (const float*)d_in[3];  const float* bk = (const float*)d_in[4];
    const float* Wv = (const float*)d_in[5];  const float* bv = (const float*)d_in[6];
    const float* Wo = (const float*)d_in[7];  const float* bo = (const float*)d_in[8];
    const float* Wt = (const float*)d_in[9];  const float* bt = (const float*)d_in[10];
    const float* Wg = (const float*)d_in[11]; const float* bg = (const float*)d_in[12];
    float* out = (float*)d_out;

    __half *xh,*Wcat,*Woh,*qkvgh,*obsdh,*out2h;
    float *bcat;
    cudaGetSymbolAddress((void**)&xh,    g_xh);
    cudaGetSymbolAddress((void**)&Wcat,  g_Wcat);
    cudaGetSymbolAddress((void**)&bcat,  g_bcat);
    cudaGetSymbolAddress((void**)&Woh,   g_Woh);
    cudaGetSymbolAddress((void**)&qkvgh, g_qkvgh);
    cudaGetSymbolAddress((void**)&obsdh, g_obsdh);
    cudaGetSymbolAddress((void**)&out2h, g_out2h);

    cudaFuncSetAttribute(fused_attn, cudaFuncAttributeMaxDynamicSharedMemorySize, SMEM_ATTN);

    // conversions / packing
    f2h_kernel<<<(M_*D_)/1024, 256>>>(x,  xh);
    f2h_pack<<<(D_*D_)/1024, 256>>>(Wq, Wcat, 0);
    f2h_pack<<<(D_*D_)/1024, 256>>>(Wk, Wcat, 1024);
    f2h_pack<<<(D_*D_)/1024, 256>>>(Wv, Wcat, 2048);
    f2h_pack<<<(D_*D_)/1024, 256>>>(Wg, Wcat, 3072);
    f2h_kernel<<<(D_*D_)/1024, 256>>>(Wo, Woh);
    pack_bias<<<16, 256>>>(bq, bk, bv, bg);

    // temperature path (fp32)
    mean_stage1<<<B_*MCH_, 256>>>(x);
    mean_stage2<<<(B_*D_)/256, 256>>>();
    temp_kernel<<<B_, 256>>>(Wt, bt);

    // fused QKVG projection: [4096,1024] @ [1024,4096]
    hgemm_bias<<<dim3(4096/128, M_/128), 256>>>(xh, Wcat, bcat, qkvgh, M_, 4096, D_);

    // normalize + head relayout
    norm_split<<<(BH_*S_*32)/256, 256>>>();

    // fused attention (scores never leave the SM)
    fused_attn<<<dim3(S_/16, BH_), 512, SMEM_ATTN>>>();

    // output projection + highway gate
    hgemm_bias<<<dim3(D_/128, M_/128), 256>>>(obsdh, Woh, bo, out2h, M_, D_, D_);
    finalize_kernel<<<(M_*D_/2)/256, 256>>>(x, out);
}

// round 5
// speedup vs baseline: 1.4113x; 1.3938x over previous
#include <cuda_runtime.h>
#include <cuda_fp16.h>
#include <math.h>

#define B_   2
#define S_   2048
#define D_   1024
#define H_   16
#define DH_  64
#define M_   (B_*S_)          // 4096 tokens
#define BH_  (B_*H_)          // 32
#define KK_  512              // top-k
#define MCH_ 16               // mean chunks

#define SA   40               // smem row stride (halves) for 32-col tiles
#define SBP  136              // smem row stride for 128-col B tiles
#define SBV  72               // smem row stride for 64-col V tiles

// ---------------- scratch (static device memory; no allocations) ----------------
__device__ __half g_xh[M_*D_];
__device__ __half g_Wcat[D_*4*D_];         // packed [1024][4096] : Wq|Wk|Wv|Wg
__device__ float  g_bcat[4*D_];
__device__ __half g_Woh[D_*D_];
__device__ __half g_qkvgh[(size_t)M_*4*D_]; // [4096][4096] : q|k|v|gate
__device__ __half g_qnh[M_*D_];     // [BH][S][DH]
__device__ __half g_knh[M_*D_];     // [BH][S][DH]
__device__ __half g_vhh[M_*D_];     // [BH][S][DH]
__device__ __half g_obsdh[M_*D_];   // attention output in [B,S,D]
__device__ __half g_out2h[M_*D_];   // after Wo
__device__ float  g_scores[(size_t)BH_*S_*S_];   // 512MB fp32 scores
__device__ __half g_attnh[(size_t)BH_*S_*S_];    // 256MB fp16 attention weights
__device__ float  g_xpart[MCH_*B_*D_];
__device__ float  g_xmean[B_*D_];
__device__ float  g_temp[B_];

// ---------------- mma / ldmatrix helpers ----------------
__device__ __forceinline__ void mma_f16(float* d, const unsigned* a, unsigned b0, unsigned b1){
    asm volatile("mma.sync.aligned.m16n8k16.row.col.f32.f16.f16.f32 "
        "{%0,%1,%2,%3}, {%4,%5,%6,%7}, {%8,%9}, {%0,%1,%2,%3};\n"
        : "+f"(d[0]),"+f"(d[1]),"+f"(d[2]),"+f"(d[3])
        : "r"(a[0]),"r"(a[1]),"r"(a[2]),"r"(a[3]), "r"(b0),"r"(b1));
}
__device__ __forceinline__ void ldsm4(unsigned* r, const __half* p){
    unsigned addr = (unsigned)__cvta_generic_to_shared(p);
    asm volatile("ldmatrix.sync.aligned.m8n8.x4.shared.b16 {%0,%1,%2,%3}, [%4];\n"
        :"=r"(r[0]),"=r"(r[1]),"=r"(r[2]),"=r"(r[3]) : "r"(addr));
}
__device__ __forceinline__ void ldsm4t(unsigned* r, const __half* p){
    unsigned addr = (unsigned)__cvta_generic_to_shared(p);
    asm volatile("ldmatrix.sync.aligned.m8n8.x4.trans.shared.b16 {%0,%1,%2,%3}, [%4];\n"
        :"=r"(r[0]),"=r"(r[1]),"=r"(r[2]),"=r"(r[3]) : "r"(addr));
}

// ---------------- fp32 -> fp16 conversion ----------------
__global__ __launch_bounds__(256) void f2h_kernel(const float* __restrict__ in,
                                                  __half* __restrict__ out){
    int i = blockIdx.x*256 + threadIdx.x;
    float4 v = reinterpret_cast<const float4*>(in)[i];
    reinterpret_cast<__half2*>(out)[2*i]   = __floats2half2_rn(v.x, v.y);
    reinterpret_cast<__half2*>(out)[2*i+1] = __floats2half2_rn(v.z, v.w);
}

// pack TWO 1024x1024 fp32 weights into column blocks col0, col0+1024 of [1024][4096]
__global__ __launch_bounds__(256) void f2h_pack2(const float* __restrict__ inA,
                                                 const float* __restrict__ inB,
                                                 int col0){
    int gi = blockIdx.x*256 + threadIdx.x;     // over 2 * 1024*1024/4 float4s
    int half = gi >> 18;                        // 0: A, 1: B  (262144 each)
    int i = gi & 262143;
    const float* in = half ? inB : inA;
    int row = i >> 8, c4 = (i & 255) * 4;
    float4 v = reinterpret_cast<const float4*>(in)[i];
    __half* o = g_Wcat + (size_t)row*4096 + col0 + half*1024 + c4;
    *(__half2*)&o[0] = __floats2half2_rn(v.x, v.y);
    *(__half2*)&o[2] = __floats2half2_rn(v.z, v.w);
}

__global__ __launch_bounds__(256) void pack_bias(const float* __restrict__ bq,
                                                 const float* __restrict__ bk,
                                                 const float* __restrict__ bv,
                                                 const float* __restrict__ bg){
    int idx = blockIdx.x*256 + threadIdx.x;    // 4096
    int seg = idx >> 10, j = idx & 1023;
    float v = (seg==0) ? bq[j] : (seg==1) ? bk[j] : (seg==2) ? bv[j] : bg[j];
    g_bcat[idx] = v;
}

// ---------------- mean over sequence + temperature ----------------
__global__ __launch_bounds__(256) void mean_stage1(const float* __restrict__ x){
    int b  = blockIdx.x / MCH_;
    int ch = blockIdx.x % MCH_;
    int s0 = ch * (S_/MCH_);
    int tid = threadIdx.x;
    float acc[4] = {0.f,0.f,0.f,0.f};
    for (int s = s0; s < s0 + S_/MCH_; ++s){
        const float* xp = x + ((size_t)(b*S_+s))*D_;
        #pragma unroll
        for (int j = 0; j < 4; ++j) acc[j] += xp[tid + j*256];
    }
    #pragma unroll
    for (int j = 0; j < 4; ++j) g_xpart[((size_t)ch*B_ + b)*D_ + tid + j*256] = acc[j];
}

__global__ __launch_bounds__(256) void mean_stage2(){
    int idx = blockIdx.x*256 + threadIdx.x;
    int b = idx / D_, d = idx % D_;
    float s = 0.f;
    #pragma unroll
    for (int ch = 0; ch < MCH_; ++ch) s += g_xpart[((size_t)ch*B_ + b)*D_ + d];
    g_xmean[idx] = s * (1.0f/S_);
}

__global__ __launch_bounds__(256) void temp_kernel(const float* __restrict__ Wt,
                                                   const float* __restrict__ bt){
    __shared__ float red[256];
    int b = blockIdx.x, tid = threadIdx.x;
    float s = 0.f;
    for (int d = tid; d < D_; d += 256) s += g_xmean[b*D_ + d] * Wt[d];
    red[tid] = s; __syncthreads();
    for (int o = 128; o; o >>= 1){ if (tid < o) red[tid] += red[tid+o]; __syncthreads(); }
    if (tid == 0) g_temp[b] = 1.0f/(1.0f + expf(-(red[0] + bt[0]))) + 0.5f;
}

// ---------------- fp16 tensor-core GEMM: C(fp16) = A @ W + bias ----------------
// BM=128, BN=128, BK=32, 256 threads, 8 warps (2M x 4N), warp tile 64x32
__global__ __launch_bounds__(256) void hgemm_bias(const __half* __restrict__ A,
                                                  const __half* __restrict__ Bw,
                                                  const float* __restrict__ bias,
                                                  __half* __restrict__ C,
                                                  int M, int N, int K){
    __shared__ __half As[2][128*SA];
    __shared__ __half Bs[2][32*SBP];
    const int tid = threadIdx.x, lane = tid & 31, wid = tid >> 5;
    const int m0 = blockIdx.y*128, n0 = blockIdx.x*128;
    const int wm = (wid & 1)*64, wn = (wid >> 1)*32;
    const int KT = K >> 5;
    float acc[4][4][4] = {};

    const int ar = tid >> 2, ac = (tid & 3) << 3;
    const int br = tid >> 4, bc = (tid & 15) << 3;

    #pragma unroll
    for (int c = 0; c < 2; ++c){
        *(float4*)&As[0][(ar+c*64)*SA + ac] =
            *(const float4*)(A + (size_t)(m0+ar+c*64)*K + ac);
        *(float4*)&Bs[0][(br+c*16)*SBP + bc] =
            *(const float4*)(Bw + (size_t)(br+c*16)*N + n0 + bc);
    }
    __syncthreads();

    for (int kt = 0; kt < KT; ++kt){
        const int cur = kt & 1;
        float4 ra[2], rb[2];
        const bool nxt = (kt+1 < KT);
        if (nxt){
            int k0 = (kt+1) << 5;
            #pragma unroll
            for (int c = 0; c < 2; ++c){
                ra[c] = *(const float4*)(A + (size_t)(m0+ar+c*64)*K + k0 + ac);
                rb[c] = *(const float4*)(Bw + (size_t)(k0+br+c*16)*N + n0 + bc);
            }
        }
        #pragma unroll
        for (int ks = 0; ks < 2; ++ks){
            unsigned af[4][4], bf[2][4];
            #pragma unroll
            for (int mt = 0; mt < 4; ++mt)
                ldsm4(af[mt], &As[cur][(wm+mt*16+(lane&15))*SA + ks*16 + (lane>>4)*8]);
            #pragma unroll
            for (int g = 0; g < 2; ++g)
                ldsm4t(bf[g], &Bs[cur][(ks*16+(lane&15))*SBP + wn + g*16 + (lane>>4)*8]);
            #pragma unroll
            for (int mt = 0; mt < 4; ++mt)
                #pragma unroll
                for (int g = 0; g < 2; ++g){
                    mma_f16(acc[mt][2*g],   af[mt], bf[g][0], bf[g][1]);
                    mma_f16(acc[mt][2*g+1], af[mt], bf[g][2], bf[g][3]);
                }
        }
        if (nxt){
            #pragma unroll
            for (int c = 0; c < 2; ++c){
                *(float4*)&As[cur^1][(ar+c*64)*SA + ac] = ra[c];
                *(float4*)&Bs[cur^1][(br+c*16)*SBP + bc] = rb[c];
            }
        }
        __syncthreads();
    }

    #pragma unroll
    for (int mt = 0; mt < 4; ++mt){
        int r = m0 + wm + mt*16 + (lane >> 2);
        #pragma unroll
        for (int nt = 0; nt < 4; ++nt){
            int c = n0 + wn + nt*8 + (lane & 3)*2;
            float b0 = bias[c], b1 = bias[c+1];
            *(__half2*)&C[(size_t)r*N + c] =
                __floats2half2_rn(acc[mt][nt][0]+b0, acc[mt][nt][1]+b1);
            *(__half2*)&C[(size_t)(r+8)*N + c] =
                __floats2half2_rn(acc[mt][nt][2]+b0, acc[mt][nt][3]+b1);
        }
    }
}

// ---------------- head split + L2 normalize (q,k) + v relayout (from qkvg) ----------------
__global__ __launch_bounds__(256) void norm_split(){
    int gw   = (blockIdx.x*256 + threadIdx.x) >> 5;   // one warp per (bh,s)
    int lane = threadIdx.x & 31;
    int s  = gw & (S_-1);
    int bh = gw >> 11;
    int h  = bh & (H_-1), b = bh >> 4;
    size_t row = (size_t)(b*S_+s)*4096;
    int hc = h*DH_ + lane*2;
    size_t dst = (size_t)gw * DH_ + lane*2;

    float2 qv = __half22float2(*(const __half2*)(g_qkvgh + row + hc));
    float ss = qv.x*qv.x + qv.y*qv.y;
    #pragma unroll
    for (int o = 16; o; o >>= 1) ss += __shfl_xor_sync(0xFFFFFFFFu, ss, o);
    float inv = 1.0f / fmaxf(sqrtf(ss), 1e-12f);
    *(__half2*)(g_qnh + dst) = __floats2half2_rn(qv.x*inv, qv.y*inv);

    float2 kv = __half22float2(*(const __half2*)(g_qkvgh + row + 1024 + hc));
    ss = kv.x*kv.x + kv.y*kv.y;
    #pragma unroll
    for (int o = 16; o; o >>= 1) ss += __shfl_xor_sync(0xFFFFFFFFu, ss, o);
    inv = 1.0f / fmaxf(sqrtf(ss), 1e-12f);
    *(__half2*)(g_knh + dst) = __floats2half2_rn(kv.x*inv, kv.y*inv);

    *(__half2*)(g_vhh + dst) = *(const __half2*)(g_qkvgh + row + 2048 + hc);
}

// ---------------- scores[bh] = Qn @ Kn^T / temp[b]  (fp16 mma, fp32 out) ----------------
__global__ __launch_bounds__(256) void scores_mma(){
    const int bh = blockIdx.z, b = bh >> 4;
    const __half* Q  = g_qnh + (size_t)bh*S_*DH_;
    const __half* Kn = g_knh + (size_t)bh*S_*DH_;
    __shared__ __half As[2][128*SA];
    __shared__ __half Bs[2][128*SA];
    const int tid = threadIdx.x, lane = tid & 31, wid = tid >> 5;
    const int m0 = blockIdx.y*128, n0 = blockIdx.x*128;
    const int wm = (wid & 1)*64, wn = (wid >> 1)*32;
    float acc[4][4][4] = {};

    const int ar = tid >> 2, ac = (tid & 3) << 3;

    #pragma unroll
    for (int c = 0; c < 2; ++c){
        *(float4*)&As[0][(ar+c*64)*SA + ac] =
            *(const float4*)(Q + (size_t)(m0+ar+c*64)*DH_ + ac);
        *(float4*)&Bs[0][(ar+c*64)*SA + ac] =
            *(const float4*)(Kn + (size_t)(n0+ar+c*64)*DH_ + ac);
    }
    __syncthreads();

    const int KT = DH_ >> 5;  // 2
    for (int kt = 0; kt < KT; ++kt){
        const int cur = kt & 1;
        float4 ra[2], rb[2];
        const bool nxt = (kt+1 < KT);
        if (nxt){
            int k0 = (kt+1) << 5;
            #pragma unroll
            for (int c = 0; c < 2; ++c){
                ra[c] = *(const float4*)(Q  + (size_t)(m0+ar+c*64)*DH_ + k0 + ac);
                rb[c] = *(const float4*)(Kn + (size_t)(n0+ar+c*64)*DH_ + k0 + ac);
            }
        }
        #pragma unroll
        for (int ks = 0; ks < 2; ++ks){
            unsigned af[4][4], bf[2][4];
            #pragma unroll
            for (int mt = 0; mt < 4; ++mt)
                ldsm4(af[mt], &As[cur][(wm+mt*16+(lane&15))*SA + ks*16 + (lane>>4)*8]);
            #pragma unroll
            for (int g = 0; g < 2; ++g)
                ldsm4(bf[g], &Bs[cur][(wn + g*16 + ((lane>>4)<<3) + (lane&7))*SA
                                      + ks*16 + ((lane>>3)&1)*8]);
            #pragma unroll
            for (int mt = 0; mt < 4; ++mt)
                #pragma unroll
                for (int g = 0; g < 2; ++g){
                    mma_f16(acc[mt][2*g],   af[mt], bf[g][0], bf[g][1]);
                    mma_f16(acc[mt][2*g+1], af[mt], bf[g][2], bf[g][3]);
                }
        }
        if (nxt){
            #pragma unroll
            for (int c = 0; c < 2; ++c){
                *(float4*)&As[cur^1][(ar+c*64)*SA + ac] = ra[c];
                *(float4*)&Bs[cur^1][(ar+c*64)*SA + ac] = rb[c];
            }
        }
        __syncthreads();
    }

    const float sc = 1.0f / g_temp[b];
    #pragma unroll
    for (int mt = 0; mt < 4; ++mt){
        int r = m0 + wm + mt*16 + (lane >> 2);
        #pragma unroll
        for (int nt = 0; nt < 4; ++nt){
            int c = n0 + wn + nt*8 + (lane & 3)*2;
            float2 o0 = make_float2(acc[mt][nt][0]*sc, acc[mt][nt][1]*sc);
            float2 o1 = make_float2(acc[mt][nt][2]*sc, acc[mt][nt][3]*sc);
            *(float2*)&g_scores[((size_t)bh*S_ + r)*S_ + c]     = o0;
            *(float2*)&g_scores[((size_t)bh*S_ + r + 8)*S_ + c] = o1;
        }
    }
}

// ---------------- exact top-512 radix-select + softmax -> fp16 weights ----------------
__global__ __launch_bounds__(256) void topk_softmax(){
    const size_t row = blockIdx.x;
    const float* sp = g_scores + row*(size_t)S_;
    __half* ap = g_attnh + row*(size_t)S_;
    __shared__ unsigned hist[256];
    __shared__ unsigned sufs[256];
    __shared__ unsigned wsum[8];
    __shared__ float fr[8];
    __shared__ unsigned s_bin, s_above;
    __shared__ float s_mx, s_sum;
    const int tid = threadIdx.x, lane = tid & 31, wid = tid >> 5;

    float v[8]; unsigned key[8];
    #pragma unroll
    for (int i = 0; i < 8; ++i){
        v[i] = sp[i*256 + tid];
        unsigned u = __float_as_uint(v[i]);
        key[i] = u ^ (((unsigned)((int)u >> 31)) | 0x80000000u);
    }

    unsigned prefix = 0, remaining = KK_;
    #pragma unroll
    for (int shift = 24; shift >= 0; shift -= 8){
        hist[tid] = 0; __syncthreads();
        unsigned pmask = (shift == 24) ? 0u : (0xFFFFFFFFu << (shift+8));
        #pragma unroll
        for (int i = 0; i < 8; ++i)
            if ((key[i] & pmask) == prefix) atomicAdd(&hist[(key[i] >> shift) & 255], 1u);
        __syncthreads();
        unsigned x = hist[255 - tid];
        #pragma unroll
        for (int o = 1; o < 32; o <<= 1){
            unsigned t = __shfl_up_sync(0xFFFFFFFFu, x, o);
            if (lane >= o) x += t;
        }
        if (lane == 31) wsum[wid] = x;
        __syncthreads();
        if (tid < 8){
            unsigned w = wsum[tid];
            #pragma unroll
            for (int o = 1; o < 8; o <<= 1){
                unsigned t = __shfl_up_sync(0xFFu, w, o);
                if (tid >= o) w += t;
            }
            wsum[tid] = w;
        }
        __syncthreads();
        unsigned suf = x + (wid ? wsum[wid-1] : 0u);
        sufs[255 - tid] = suf;
        __syncthreads();
        unsigned Sb  = sufs[tid];
        unsigned Sb1 = (tid < 255) ? sufs[tid+1] : 0u;
        if (Sb >= remaining && Sb1 < remaining){ s_bin = (unsigned)tid; s_above = Sb1; }
        __syncthreads();
        remaining -= s_above;
        prefix |= (s_bin << shift);
    }
    const unsigned T = prefix;

    float mx = -3.402823466e38f;
    #pragma unroll
    for (int i = 0; i < 8; ++i) mx = fmaxf(mx, v[i]);
    #pragma unroll
    for (int o = 16; o; o >>= 1) mx = fmaxf(mx, __shfl_xor_sync(0xFFFFFFFFu, mx, o));
    if (lane == 0) fr[wid] = mx;
    __syncthreads();
    if (tid == 0){
        float m = fr[0];
        #pragma unroll
        for (int j = 1; j < 8; ++j) m = fmaxf(m, fr[j]);
        s_mx = m;
    }
    __syncthreads();
    mx = s_mx;

    float e[8]; float ls = 0.f;
    #pragma unroll
    for (int i = 0; i < 8; ++i){
        e[i] = (key[i] >= T) ? expf(v[i] - mx) : 0.0f;
        ls += e[i];
    }
    #pragma unroll
    for (int o = 16; o; o >>= 1) ls += __shfl_xor_sync(0xFFFFFFFFu, ls, o);
    if (lane == 0) fr[wid] = ls;
    __syncthreads();
    if (tid == 0){
        float m = 0.f;
        #pragma unroll
        for (int j = 0; j < 8; ++j) m += fr[j];
        s_sum = m;
    }
    __syncthreads();
    const float inv = 1.0f / s_sum;
    #pragma unroll
    for (int i = 0; i < 8; ++i) ap[i*256 + tid] = __float2half(e[i]*inv);
}

// ---------------- O = attn @ V  (fp16 mma) ----------------
// BM=128, BN=64, BK=32, 8 warps (4M x 2N), warp tile 32x32, K=2048
__global__ __launch_bounds__(256) void av_mma(){
    const int bh = blockIdx.z;
    const int m0 = blockIdx.y*128;
    const __half* A = g_attnh + (size_t)bh*S_*S_;
    const __half* V = g_vhh   + (size_t)bh*S_*DH_;
    __shared__ __half As[2][128*SA];
    __shared__ __half Bs[2][32*SBV];
    const int tid = threadIdx.x, lane = tid & 31, wid = tid >> 5;
    const int wm = (wid & 3)*32, wn = (wid >> 2)*32;
    float acc[2][4][4] = {};

    const int ar = tid >> 2, ac = (tid & 3) << 3;
    const int br = tid >> 3, bc = (tid & 7) << 3;

    #pragma unroll
    for (int c = 0; c < 2; ++c)
        *(float4*)&As[0][(ar+c*64)*SA + ac] =
            *(const float4*)(A + (size_t)(m0+ar+c*64)*S_ + ac);
    *(float4*)&Bs[0][br*SBV + bc] = *(const float4*)(V + (size_t)br*DH_ + bc);
    __syncthreads();

    const int KT = S_ >> 5;  // 64
    for (int kt = 0; kt < KT; ++kt){
        const int cur = kt & 1;
        float4 ra[2], rb;
        const bool nxt = (kt+1 < KT);
        if (nxt){
            int k0 = (kt+1) << 5;
            #pragma unroll
            for (int c = 0; c < 2; ++c)
                ra[c] = *(const float4*)(A + (size_t)(m0+ar+c*64)*S_ + k0 + ac);
            rb = *(const float4*)(V + (size_t)(k0+br)*DH_ + bc);
        }
        #pragma unroll
        for (int ks = 0; ks < 2; ++ks){
            unsigned af[2][4], bf[2][4];
            #pragma unroll
            for (int mt = 0; mt < 2; ++mt)
                ldsm4(af[mt], &As[cur][(wm+mt*16+(lane&15))*SA + ks*16 + (lane>>4)*8]);
            #pragma unroll
            for (int g = 0; g < 2; ++g)
                ldsm4t(bf[g], &Bs[cur][(ks*16+(lane&15))*SBV + wn + g*16 + (lane>>4)*8]);
            #pragma unroll
            for (int mt = 0; mt < 2; ++mt)
                #pragma unroll
                for (int g = 0; g < 2; ++g){
                    mma_f16(acc[mt][2*g],   af[mt], bf[g][0], bf[g][1]);
                    mma_f16(acc[mt][2*g+1], af[mt], bf[g][2], bf[g][3]);
                }
        }
        if (nxt){
            #pragma unroll
            for (int c = 0; c < 2; ++c)
                *(float4*)&As[cur^1][(ar+c*64)*SA + ac] = ra[c];
            *(float4*)&Bs[cur^1][br*SBV + bc] = rb;
        }
        __syncthreads();
    }

    const int bb = bh >> 4, h = bh & (H_-1);
    #pragma unroll
    for (int mt = 0; mt < 2; ++mt){
        int s_idx = m0 + wm + mt*16 + (lane >> 2);
        size_t grow0 = (size_t)(bb*S_ + s_idx)*D_;
        size_t grow1 = (size_t)(bb*S_ + s_idx + 8)*D_;
        #pragma unroll
        for (int nt = 0; nt < 4; ++nt){
            int c = h*DH_ + wn + nt*8 + (lane & 3)*2;
            *(__half2*)&g_obsdh[grow0 + c] = __floats2half2_rn(acc[mt][nt][0], acc[mt][nt][1]);
            *(__half2*)&g_obsdh[grow1 + c] = __floats2half2_rn(acc[mt][nt][2], acc[mt][nt][3]);
        }
    }
}

// ---------------- highway gating ----------------
__global__ __launch_bounds__(256) void finalize_kernel(const float* __restrict__ x,
                                                       float* __restrict__ out){
    int i = blockIdx.x*256 + threadIdx.x;    // over M*D/2 pairs
    int p = 2*i;
    int r = p >> 10, cb = p & 1023;
    float2 xv = reinterpret_cast<const float2*>(x)[i];
    float2 gv = __half22float2(*(const __half2*)&g_qkvgh[(size_t)r*4096 + 3072 + cb]);
    float2 ov = __half22float2(reinterpret_cast<const __half2*>(g_out2h)[i]);
    float2 rr;
    float g;
    g = 1.0f/(1.0f+expf(-gv.x)); rr.x = g*ov.x + (1.0f-g)*xv.x;
    g = 1.0f/(1.0f+expf(-gv.y)); rr.y = g*ov.y + (1.0f-g)*xv.y;
    reinterpret_cast<float2*>(out)[i] = rr;
}

// ---------------- launch ----------------
extern "C" void kernel_launch(void* const* d_in, const int* in_sizes, int n_in,
                              void* d_out, int out_size){
    (void)in_sizes; (void)n_in; (void)out_size;
    const float* x  = (const float*)d_in[0];
    const float* Wq = (const float*)d_in[1];  const float* bq = (const float*)d_in[2];
    const float* Wk = (const float*)d_in[3];  const float* bk = (const float*)d_in[4];
    const float* Wv = (const float*)d_in[5];  const float* bv = (const float*)d_in[6];
    const float* Wo = (const float*)d_in[7];  const float* bo = (const float*)d_in[8];
    const float* Wt = (const float*)d_in[9];  const float* bt = (const float*)d_in[10];
    const float* Wg = (const float*)d_in[11]; const float* bg = (const float*)d_in[12];
    float* out = (float*)d_out;

    __half *xh,*Wcat,*Woh,*qkvgh,*obsdh,*out2h;
    float *bcat;
    cudaGetSymbolAddress((void**)&xh,    g_xh);
    cudaGetSymbolAddress((void**)&Wcat,  g_Wcat);
    cudaGetSymbolAddress((void**)&bcat,  g_bcat);
    cudaGetSymbolAddress((void**)&Woh,   g_Woh);
    cudaGetSymbolAddress((void**)&qkvgh, g_qkvgh);
    cudaGetSymbolAddress((void**)&obsdh, g_obsdh);
    cudaGetSymbolAddress((void**)&out2h, g_out2h);

    // launches 0-3: conversions feeding the fused QKVG GEMM
    f2h_kernel<<<(M_*D_)/1024, 256>>>(x, xh);                      // 0
    f2h_pack2<<<2*(D_*D_)/1024, 256>>>(Wq, Wk, 0);                 // 1
    f2h_pack2<<<2*(D_*D_)/1024, 256>>>(Wv, Wg, 2048);              // 2
    pack_bias<<<16, 256>>>(bq, bk, bv, bg);                        // 3

    // launch 4: fused QKVG projection [4096,1024]@[1024,4096]  <-- profiled by ncu
    hgemm_bias<<<dim3(4096/128, M_/128), 256>>>(xh, Wcat, bcat, qkvgh, M_, 4096, D_);

    f2h_kernel<<<(D_*D_)/1024, 256>>>(Wo, Woh);

    // temperature path (fp32)
    mean_stage1<<<B_*MCH_, 256>>>(x);
    mean_stage2<<<(B_*D_)/256, 256>>>();
    temp_kernel<<<B_, 256>>>(Wt, bt);

    // normalize + head relayout
    norm_split<<<(BH_*S_*32)/256, 256>>>();

    // scores, top-k softmax, attn @ V  (round-2 proven pipeline)
    scores_mma<<<dim3(S_/128, S_/128, BH_), 256>>>();
    topk_softmax<<<BH_*S_, 256>>>();
    av_mma<<<dim3(1, S_/128, BH_), 256>>>();

    // output projection + highway gate
    hgemm_bias<<<dim3(D_/128, M_/128), 256>>>(obsdh, Woh, bo, out2h, M_, D_, D_);
    finalize_kernel<<<(M_*D_/2)/256, 256>>>(x, out);
}

// round 6
// speedup vs baseline: 1.6130x; 1.1429x over previous
#include <cuda_runtime.h>
#include <cuda_fp16.h>
#include <math.h>

#define B_   2
#define S_   2048
#define D_   1024
#define H_   16
#define DH_  64
#define M_   (B_*S_)          // 4096 tokens
#define BH_  (B_*H_)          // 32
#define KK_  512              // top-k
#define MCH_ 16               // mean chunks

#define SA   40               // smem row stride (halves) for 32-col tiles
#define SBP  136              // smem row stride for 128-col B tiles
#define SBV  72               // smem row stride for 64-col V tiles

// ---------------- scratch (static device memory; no allocations) ----------------
__device__ __half g_xh[M_*D_];
__device__ __half g_Wcat[D_*4*D_];         // packed [1024][4096] : Wq|Wk|Wv|Wg
__device__ float  g_bcat[4*D_];
__device__ __half g_Woh[D_*D_];
__device__ __half g_qkvgh[(size_t)M_*4*D_]; // [4096][4096] : q|k|v|gate
__device__ __half g_qnh[M_*D_];     // [BH][S][DH]
__device__ __half g_knh[M_*D_];     // [BH][S][DH]
__device__ __half g_vhh[M_*D_];     // [BH][S][DH]
__device__ __half g_obsdh[M_*D_];   // attention output in [B,S,D]
__device__ __half g_out2h[M_*D_];   // after Wo
__device__ __half g_scoresh[(size_t)BH_*S_*S_]; // 256MB fp16 scores (post-temp)
__device__ __half g_attnh[(size_t)BH_*S_*S_];   // 256MB fp16 attention weights
__device__ float  g_xpart[MCH_*B_*D_];
__device__ float  g_xmean[B_*D_];
__device__ float  g_temp[B_];

// ---------------- mma / ldmatrix helpers ----------------
__device__ __forceinline__ void mma_f16(float* d, const unsigned* a, unsigned b0, unsigned b1){
    asm volatile("mma.sync.aligned.m16n8k16.row.col.f32.f16.f16.f32 "
        "{%0,%1,%2,%3}, {%4,%5,%6,%7}, {%8,%9}, {%0,%1,%2,%3};\n"
        : "+f"(d[0]),"+f"(d[1]),"+f"(d[2]),"+f"(d[3])
        : "r"(a[0]),"r"(a[1]),"r"(a[2]),"r"(a[3]), "r"(b0),"r"(b1));
}
__device__ __forceinline__ void ldsm4(unsigned* r, const __half* p){
    unsigned addr = (unsigned)__cvta_generic_to_shared(p);
    asm volatile("ldmatrix.sync.aligned.m8n8.x4.shared.b16 {%0,%1,%2,%3}, [%4];\n"
        :"=r"(r[0]),"=r"(r[1]),"=r"(r[2]),"=r"(r[3]) : "r"(addr));
}
__device__ __forceinline__ void ldsm4t(unsigned* r, const __half* p){
    unsigned addr = (unsigned)__cvta_generic_to_shared(p);
    asm volatile("ldmatrix.sync.aligned.m8n8.x4.trans.shared.b16 {%0,%1,%2,%3}, [%4];\n"
        :"=r"(r[0]),"=r"(r[1]),"=r"(r[2]),"=r"(r[3]) : "r"(addr));
}

// ---------------- fp32 -> fp16 conversion ----------------
__global__ __launch_bounds__(256) void f2h_kernel(const float* __restrict__ in,
                                                  __half* __restrict__ out){
    int i = blockIdx.x*256 + threadIdx.x;
    float4 v = reinterpret_cast<const float4*>(in)[i];
    reinterpret_cast<__half2*>(out)[2*i]   = __floats2half2_rn(v.x, v.y);
    reinterpret_cast<__half2*>(out)[2*i+1] = __floats2half2_rn(v.z, v.w);
}

// pack FOUR 1024x1024 fp32 weights into [1024][4096] halves: Wq|Wk|Wv|Wg
__global__ __launch_bounds__(256) void f2h_pack4(const float* __restrict__ w0,
                                                 const float* __restrict__ w1,
                                                 const float* __restrict__ w2,
                                                 const float* __restrict__ w3){
    int gi = blockIdx.x*256 + threadIdx.x;     // over 4 * 262144 float4s
    int q = gi >> 18;                          // which weight
    int i = gi & 262143;
    const float* in = (q==0) ? w0 : (q==1) ? w1 : (q==2) ? w2 : w3;
    int row = i >> 8, c4 = (i & 255) * 4;
    float4 v = reinterpret_cast<const float4*>(in)[i];
    __half* o = g_Wcat + (size_t)row*4096 + q*1024 + c4;
    *(__half2*)&o[0] = __floats2half2_rn(v.x, v.y);
    *(__half2*)&o[2] = __floats2half2_rn(v.z, v.w);
}

__global__ __launch_bounds__(256) void pack_bias(const float* __restrict__ bq,
                                                 const float* __restrict__ bk,
                                                 const float* __restrict__ bv,
                                                 const float* __restrict__ bg){
    int idx = blockIdx.x*256 + threadIdx.x;    // 4096
    int seg = idx >> 10, j = idx & 1023;
    float v = (seg==0) ? bq[j] : (seg==1) ? bk[j] : (seg==2) ? bv[j] : bg[j];
    g_bcat[idx] = v;
}

// ---------------- mean over sequence + temperature ----------------
__global__ __launch_bounds__(256) void mean_stage1(const float* __restrict__ x){
    int b  = blockIdx.x / MCH_;
    int ch = blockIdx.x % MCH_;
    int s0 = ch * (S_/MCH_);
    int tid = threadIdx.x;
    float acc[4] = {0.f,0.f,0.f,0.f};
    for (int s = s0; s < s0 + S_/MCH_; ++s){
        const float* xp = x + ((size_t)(b*S_+s))*D_;
        #pragma unroll
        for (int j = 0; j < 4; ++j) acc[j] += xp[tid + j*256];
    }
    #pragma unroll
    for (int j = 0; j < 4; ++j) g_xpart[((size_t)ch*B_ + b)*D_ + tid + j*256] = acc[j];
}

__global__ __launch_bounds__(256) void mean_stage2(){
    int idx = blockIdx.x*256 + threadIdx.x;
    int b = idx / D_, d = idx % D_;
    float s = 0.f;
    #pragma unroll
    for (int ch = 0; ch < MCH_; ++ch) s += g_xpart[((size_t)ch*B_ + b)*D_ + d];
    g_xmean[idx] = s * (1.0f/S_);
}

__global__ __launch_bounds__(256) void temp_kernel(const float* __restrict__ Wt,
                                                   const float* __restrict__ bt){
    __shared__ float red[256];
    int b = blockIdx.x, tid = threadIdx.x;
    float s = 0.f;
    for (int d = tid; d < D_; d += 256) s += g_xmean[b*D_ + d] * Wt[d];
    red[tid] = s; __syncthreads();
    for (int o = 128; o; o >>= 1){ if (tid < o) red[tid] += red[tid+o]; __syncthreads(); }
    if (tid == 0) g_temp[b] = 1.0f/(1.0f + expf(-(red[0] + bt[0]))) + 0.5f;
}

// ---------------- fp16 tensor-core GEMM: C(fp16) = A @ W + bias ----------------
// BM=128, BN=128, BK=32, 256 threads, 8 warps (2M x 4N), warp tile 64x32
__global__ __launch_bounds__(256) void hgemm_bias(const __half* __restrict__ A,
                                                  const __half* __restrict__ Bw,
                                                  const float* __restrict__ bias,
                                                  __half* __restrict__ C,
                                                  int M, int N, int K){
    __shared__ __half As[2][128*SA];
    __shared__ __half Bs[2][32*SBP];
    const int tid = threadIdx.x, lane = tid & 31, wid = tid >> 5;
    const int m0 = blockIdx.y*128, n0 = blockIdx.x*128;
    const int wm = (wid & 1)*64, wn = (wid >> 1)*32;
    const int KT = K >> 5;
    float acc[4][4][4] = {};

    const int ar = tid >> 2, ac = (tid & 3) << 3;
    const int br = tid >> 4, bc = (tid & 15) << 3;

    #pragma unroll
    for (int c = 0; c < 2; ++c){
        *(float4*)&As[0][(ar+c*64)*SA + ac] =
            *(const float4*)(A + (size_t)(m0+ar+c*64)*K + ac);
        *(float4*)&Bs[0][(br+c*16)*SBP + bc] =
            *(const float4*)(Bw + (size_t)(br+c*16)*N + n0 + bc);
    }
    __syncthreads();

    for (int kt = 0; kt < KT; ++kt){
        const int cur = kt & 1;
        float4 ra[2], rb[2];
        const bool nxt = (kt+1 < KT);
        if (nxt){
            int k0 = (kt+1) << 5;
            #pragma unroll
            for (int c = 0; c < 2; ++c){
                ra[c] = *(const float4*)(A + (size_t)(m0+ar+c*64)*K + k0 + ac);
                rb[c] = *(const float4*)(Bw + (size_t)(k0+br+c*16)*N + n0 + bc);
            }
        }
        #pragma unroll
        for (int ks = 0; ks < 2; ++ks){
            unsigned af[4][4], bf[2][4];
            #pragma unroll
            for (int mt = 0; mt < 4; ++mt)
                ldsm4(af[mt], &As[cur][(wm+mt*16+(lane&15))*SA + ks*16 + (lane>>4)*8]);
            #pragma unroll
            for (int g = 0; g < 2; ++g)
                ldsm4t(bf[g], &Bs[cur][(ks*16+(lane&15))*SBP + wn + g*16 + (lane>>4)*8]);
            #pragma unroll
            for (int mt = 0; mt < 4; ++mt)
                #pragma unroll
                for (int g = 0; g < 2; ++g){
                    mma_f16(acc[mt][2*g],   af[mt], bf[g][0], bf[g][1]);
                    mma_f16(acc[mt][2*g+1], af[mt], bf[g][2], bf[g][3]);
                }
        }
        if (nxt){
            #pragma unroll
            for (int c = 0; c < 2; ++c){
                *(float4*)&As[cur^1][(ar+c*64)*SA + ac] = ra[c];
                *(float4*)&Bs[cur^1][(br+c*16)*SBP + bc] = rb[c];
            }
        }
        __syncthreads();
    }

    #pragma unroll
    for (int mt = 0; mt < 4; ++mt){
        int r = m0 + wm + mt*16 + (lane >> 2);
        #pragma unroll
        for (int nt = 0; nt < 4; ++nt){
            int c = n0 + wn + nt*8 + (lane & 3)*2;
            float b0 = bias[c], b1 = bias[c+1];
            *(__half2*)&C[(size_t)r*N + c] =
                __floats2half2_rn(acc[mt][nt][0]+b0, acc[mt][nt][1]+b1);
            *(__half2*)&C[(size_t)(r+8)*N + c] =
                __floats2half2_rn(acc[mt][nt][2]+b0, acc[mt][nt][3]+b1);
        }
    }
}

// ---------------- head split + L2 normalize (q,k) + v relayout (from qkvg) ----------------
__global__ __launch_bounds__(256) void norm_split(){
    int gw   = (blockIdx.x*256 + threadIdx.x) >> 5;   // one warp per (bh,s)
    int lane = threadIdx.x & 31;
    int s  = gw & (S_-1);
    int bh = gw >> 11;
    int h  = bh & (H_-1), b = bh >> 4;
    size_t row = (size_t)(b*S_+s)*4096;
    int hc = h*DH_ + lane*2;
    size_t dst = (size_t)gw * DH_ + lane*2;

    float2 qv = __half22float2(*(const __half2*)(g_qkvgh + row + hc));
    float ss = qv.x*qv.x + qv.y*qv.y;
    #pragma unroll
    for (int o = 16; o; o >>= 1) ss += __shfl_xor_sync(0xFFFFFFFFu, ss, o);
    float inv = 1.0f / fmaxf(sqrtf(ss), 1e-12f);
    *(__half2*)(g_qnh + dst) = __floats2half2_rn(qv.x*inv, qv.y*inv);

    float2 kv = __half22float2(*(const __half2*)(g_qkvgh + row + 1024 + hc));
    ss = kv.x*kv.x + kv.y*kv.y;
    #pragma unroll
    for (int o = 16; o; o >>= 1) ss += __shfl_xor_sync(0xFFFFFFFFu, ss, o);
    inv = 1.0f / fmaxf(sqrtf(ss), 1e-12f);
    *(__half2*)(g_knh + dst) = __floats2half2_rn(kv.x*inv, kv.y*inv);

    *(__half2*)(g_vhh + dst) = *(const __half2*)(g_qkvgh + row + 2048 + hc);
}

// ---------------- scores[bh] = Qn @ Kn^T / temp[b]  (fp16 mma, fp16 out) ----------------
__global__ __launch_bounds__(256) void scores_mma(){
    const int bh = blockIdx.z, b = bh >> 4;
    const __half* Q  = g_qnh + (size_t)bh*S_*DH_;
    const __half* Kn = g_knh + (size_t)bh*S_*DH_;
    __shared__ __half As[2][128*SA];
    __shared__ __half Bs[2][128*SA];
    const int tid = threadIdx.x, lane = tid & 31, wid = tid >> 5;
    const int m0 = blockIdx.y*128, n0 = blockIdx.x*128;
    const int wm = (wid & 1)*64, wn = (wid >> 1)*32;
    float acc[4][4][4] = {};

    const int ar = tid >> 2, ac = (tid & 3) << 3;

    #pragma unroll
    for (int c = 0; c < 2; ++c){
        *(float4*)&As[0][(ar+c*64)*SA + ac] =
            *(const float4*)(Q + (size_t)(m0+ar+c*64)*DH_ + ac);
        *(float4*)&Bs[0][(ar+c*64)*SA + ac] =
            *(const float4*)(Kn + (size_t)(n0+ar+c*64)*DH_ + ac);
    }
    __syncthreads();

    const int KT = DH_ >> 5;  // 2
    for (int kt = 0; kt < KT; ++kt){
        const int cur = kt & 1;
        float4 ra[2], rb[2];
        const bool nxt = (kt+1 < KT);
        if (nxt){
            int k0 = (kt+1) << 5;
            #pragma unroll
            for (int c = 0; c < 2; ++c){
                ra[c] = *(const float4*)(Q  + (size_t)(m0+ar+c*64)*DH_ + k0 + ac);
                rb[c] = *(const float4*)(Kn + (size_t)(n0+ar+c*64)*DH_ + k0 + ac);
            }
        }
        #pragma unroll
        for (int ks = 0; ks < 2; ++ks){
            unsigned af[4][4], bf[2][4];
            #pragma unroll
            for (int mt = 0; mt < 4; ++mt)
                ldsm4(af[mt], &As[cur][(wm+mt*16+(lane&15))*SA + ks*16 + (lane>>4)*8]);
            #pragma unroll
            for (int g = 0; g < 2; ++g)
                ldsm4(bf[g], &Bs[cur][(wn + g*16 + ((lane>>4)<<3) + (lane&7))*SA
                                      + ks*16 + ((lane>>3)&1)*8]);
            #pragma unroll
            for (int mt = 0; mt < 4; ++mt)
                #pragma unroll
                for (int g = 0; g < 2; ++g){
                    mma_f16(acc[mt][2*g],   af[mt], bf[g][0], bf[g][1]);
                    mma_f16(acc[mt][2*g+1], af[mt], bf[g][2], bf[g][3]);
                }
        }
        if (nxt){
            #pragma unroll
            for (int c = 0; c < 2; ++c){
                *(float4*)&As[cur^1][(ar+c*64)*SA + ac] = ra[c];
                *(float4*)&Bs[cur^1][(ar+c*64)*SA + ac] = rb[c];
            }
        }
        __syncthreads();
    }

    const float sc = 1.0f / g_temp[b];
    #pragma unroll
    for (int mt = 0; mt < 4; ++mt){
        int r = m0 + wm + mt*16 + (lane >> 2);
        #pragma unroll
        for (int nt = 0; nt < 4; ++nt){
            int c = n0 + wn + nt*8 + (lane & 3)*2;
            *(__half2*)&g_scoresh[((size_t)bh*S_ + r)*S_ + c] =
                __floats2half2_rn(acc[mt][nt][0]*sc, acc[mt][nt][1]*sc);
            *(__half2*)&g_scoresh[((size_t)bh*S_ + r + 8)*S_ + c] =
                __floats2half2_rn(acc[mt][nt][2]*sc, acc[mt][nt][3]*sc);
        }
    }
}

// ---------------- exact top-512 radix-select (16-bit keys, 2 passes) + softmax ----------------
__global__ __launch_bounds__(256) void topk_softmax(){
    const size_t row = blockIdx.x;
    const __half* sp = g_scoresh + row*(size_t)S_;
    __half* ap = g_attnh + row*(size_t)S_;
    __shared__ unsigned hist[256];
    __shared__ unsigned sufs[256];
    __shared__ unsigned wsum[8];
    __shared__ float fr[8];
    __shared__ unsigned s_bin, s_above;
    __shared__ float s_mx, s_sum;
    const int tid = threadIdx.x, lane = tid & 31, wid = tid >> 5;

    float v[8]; unsigned key[8];
    #pragma unroll
    for (int i = 0; i < 8; ++i){
        __half hv = sp[i*256 + tid];
        v[i] = __half2float(hv);
        unsigned u = (unsigned)__half_as_ushort(hv);
        key[i] = u ^ ((u & 0x8000u) ? 0xFFFFu : 0x8000u);   // 16-bit monotone map
    }

    unsigned prefix = 0, remaining = KK_;
    #pragma unroll
    for (int pass = 0; pass < 2; ++pass){
        const int shift = 8 - pass*8;
        hist[tid] = 0; __syncthreads();
        unsigned pmask = (pass == 0) ? 0u : 0xFF00u;
        #pragma unroll
        for (int i = 0; i < 8; ++i)
            if ((key[i] & pmask) == prefix) atomicAdd(&hist[(key[i] >> shift) & 255], 1u);
        __syncthreads();
        unsigned x = hist[255 - tid];
        #pragma unroll
        for (int o = 1; o < 32; o <<= 1){
            unsigned t = __shfl_up_sync(0xFFFFFFFFu, x, o);
            if (lane >= o) x += t;
        }
        if (lane == 31) wsum[wid] = x;
        __syncthreads();
        if (tid < 8){
            unsigned w = wsum[tid];
            #pragma unroll
            for (int o = 1; o < 8; o <<= 1){
                unsigned t = __shfl_up_sync(0xFFu, w, o);
                if (tid >= o) w += t;
            }
            wsum[tid] = w;
        }
        __syncthreads();
        unsigned suf = x + (wid ? wsum[wid-1] : 0u);
        sufs[255 - tid] = suf;
        __syncthreads();
        unsigned Sb  = sufs[tid];
        unsigned Sb1 = (tid < 255) ? sufs[tid+1] : 0u;
        if (Sb >= remaining && Sb1 < remaining){ s_bin = (unsigned)tid; s_above = Sb1; }
        __syncthreads();
        remaining -= s_above;
        prefix |= (s_bin << shift);
        __syncthreads();
    }
    const unsigned T = prefix;

    float mx = -3.402823466e38f;
    #pragma unroll
    for (int i = 0; i < 8; ++i) mx = fmaxf(mx, v[i]);
    #pragma unroll
    for (int o = 16; o; o >>= 1) mx = fmaxf(mx, __shfl_xor_sync(0xFFFFFFFFu, mx, o));
    if (lane == 0) fr[wid] = mx;
    __syncthreads();
    if (tid == 0){
        float m = fr[0];
        #pragma unroll
        for (int j = 1; j < 8; ++j) m = fmaxf(m, fr[j]);
        s_mx = m;
    }
    __syncthreads();
    mx = s_mx;

    float e[8]; float ls = 0.f;
    #pragma unroll
    for (int i = 0; i < 8; ++i){
        e[i] = (key[i] >= T) ? expf(v[i] - mx) : 0.0f;
        ls += e[i];
    }
    #pragma unroll
    for (int o = 16; o; o >>= 1) ls += __shfl_xor_sync(0xFFFFFFFFu, ls, o);
    if (lane == 0) fr[wid] = ls;
    __syncthreads();
    if (tid == 0){
        float m = 0.f;
        #pragma unroll
        for (int j = 0; j < 8; ++j) m += fr[j];
        s_sum = m;
    }
    __syncthreads();
    const float inv = 1.0f / s_sum;
    #pragma unroll
    for (int i = 0; i < 8; ++i) ap[i*256 + tid] = __float2half(e[i]*inv);
}

// ---------------- O = attn @ V  (fp16 mma) ----------------
// BM=128, BN=64, BK=32, 8 warps (4M x 2N), warp tile 32x32, K=2048
__global__ __launch_bounds__(256) void av_mma(){
    const int bh = blockIdx.z;
    const int m0 = blockIdx.y*128;
    const __half* A = g_attnh + (size_t)bh*S_*S_;
    const __half* V = g_vhh   + (size_t)bh*S_*DH_;
    __shared__ __half As[2][128*SA];
    __shared__ __half Bs[2][32*SBV];
    const int tid = threadIdx.x, lane = tid & 31, wid = tid >> 5;
    const int wm = (wid & 3)*32, wn = (wid >> 2)*32;
    float acc[2][4][4] = {};

    const int ar = tid >> 2, ac = (tid & 3) << 3;
    const int br = tid >> 3, bc = (tid & 7) << 3;

    #pragma unroll
    for (int c = 0; c < 2; ++c)
        *(float4*)&As[0][(ar+c*64)*SA + ac] =
            *(const float4*)(A + (size_t)(m0+ar+c*64)*S_ + ac);
    *(float4*)&Bs[0][br*SBV + bc] = *(const float4*)(V + (size_t)br*DH_ + bc);
    __syncthreads();

    const int KT = S_ >> 5;  // 64
    for (int kt = 0; kt < KT; ++kt){
        const int cur = kt & 1;
        float4 ra[2], rb;
        const bool nxt = (kt+1 < KT);
        if (nxt){
            int k0 = (kt+1) << 5;
            #pragma unroll
            for (int c = 0; c < 2; ++c)
                ra[c] = *(const float4*)(A + (size_t)(m0+ar+c*64)*S_ + k0 + ac);
            rb = *(const float4*)(V + (size_t)(k0+br)*DH_ + bc);
        }
        #pragma unroll
        for (int ks = 0; ks < 2; ++ks){
            unsigned af[2][4], bf[2][4];
            #pragma unroll
            for (int mt = 0; mt < 2; ++mt)
                ldsm4(af[mt], &As[cur][(wm+mt*16+(lane&15))*SA + ks*16 + (lane>>4)*8]);
            #pragma unroll
            for (int g = 0; g < 2; ++g)
                ldsm4t(bf[g], &Bs[cur][(ks*16+(lane&15))*SBV + wn + g*16 + (lane>>4)*8]);
            #pragma unroll
            for (int mt = 0; mt < 2; ++mt)
                #pragma unroll
                for (int g = 0; g < 2; ++g){
                    mma_f16(acc[mt][2*g],   af[mt], bf[g][0], bf[g][1]);
                    mma_f16(acc[mt][2*g+1], af[mt], bf[g][2], bf[g][3]);
                }
        }
        if (nxt){
            #pragma unroll
            for (int c = 0; c < 2; ++c)
                *(float4*)&As[cur^1][(ar+c*64)*SA + ac] = ra[c];
            *(float4*)&Bs[cur^1][br*SBV + bc] = rb;
        }
        __syncthreads();
    }

    const int bb = bh >> 4, h = bh & (H_-1);
    #pragma unroll
    for (int mt = 0; mt < 2; ++mt){
        int s_idx = m0 + wm + mt*16 + (lane >> 2);
        size_t grow0 = (size_t)(bb*S_ + s_idx)*D_;
        size_t grow1 = (size_t)(bb*S_ + s_idx + 8)*D_;
        #pragma unroll
        for (int nt = 0; nt < 4; ++nt){
            int c = h*DH_ + wn + nt*8 + (lane & 3)*2;
            *(__half2*)&g_obsdh[grow0 + c] = __floats2half2_rn(acc[mt][nt][0], acc[mt][nt][1]);
            *(__half2*)&g_obsdh[grow1 + c] = __floats2half2_rn(acc[mt][nt][2], acc[mt][nt][3]);
        }
    }
}

// ---------------- highway gating ----------------
__global__ __launch_bounds__(256) void finalize_kernel(const float* __restrict__ x,
                                                       float* __restrict__ out){
    int i = blockIdx.x*256 + threadIdx.x;    // over M*D/2 pairs
    int p = 2*i;
    int r = p >> 10, cb = p & 1023;
    float2 xv = reinterpret_cast<const float2*>(x)[i];
    float2 gv = __half22float2(*(const __half2*)&g_qkvgh[(size_t)r*4096 + 3072 + cb]);
    float2 ov = __half22float2(reinterpret_cast<const __half2*>(g_out2h)[i]);
    float2 rr;
    float g;
    g = 1.0f/(1.0f+expf(-gv.x)); rr.x = g*ov.x + (1.0f-g)*xv.x;
    g = 1.0f/(1.0f+expf(-gv.y)); rr.y = g*ov.y + (1.0f-g)*xv.y;
    reinterpret_cast<float2*>(out)[i] = rr;
}

// ---------------- launch ----------------
extern "C" void kernel_launch(void* const* d_in, const int* in_sizes, int n_in,
                              void* d_out, int out_size){
    (void)in_sizes; (void)n_in; (void)out_size;
    const float* x  = (const float*)d_in[0];
    const float* Wq = (const float*)d_in[1];  const float* bq = (const float*)d_in[2];
    const float* Wk = (const float*)d_in[3];  const float* bk = (const float*)d_in[4];
    const float* Wv = (const float*)d_in[5];  const float* bv = (const float*)d_in[6];
    const float* Wo = (const float*)d_in[7];  const float* bo = (const float*)d_in[8];
    const float* Wt = (const float*)d_in[9];  const float* bt = (const float*)d_in[10];
    const float* Wg = (const float*)d_in[11]; const float* bg = (const float*)d_in[12];
    float* out = (float*)d_out;

    __half *xh,*Wcat,*Woh,*qkvgh,*obsdh,*out2h;
    float *bcat;
    cudaGetSymbolAddress((void**)&xh,    g_xh);
    cudaGetSymbolAddress((void**)&Wcat,  g_Wcat);
    cudaGetSymbolAddress((void**)&bcat,  g_bcat);
    cudaGetSymbolAddress((void**)&Woh,   g_Woh);
    cudaGetSymbolAddress((void**)&qkvgh, g_qkvgh);
    cudaGetSymbolAddress((void**)&obsdh, g_obsdh);
    cudaGetSymbolAddress((void**)&out2h, g_out2h);

    // launches 0-2: prep for QKVG GEMM
    pack_bias<<<16, 256>>>(bq, bk, bv, bg);                        // 0
    f2h_kernel<<<(M_*D_)/1024, 256>>>(x, xh);                      // 1
    f2h_pack4<<<4*(D_*D_)/1024, 256>>>(Wq, Wk, Wv, Wg);            // 2

    // launch 3: fused QKVG projection [4096,1024]@[1024,4096]  <-- profiled by ncu
    hgemm_bias<<<dim3(4096/128, M_/128), 256>>>(xh, Wcat, bcat, qkvgh, M_, 4096, D_);

    f2h_kernel<<<(D_*D_)/1024, 256>>>(Wo, Woh);

    // temperature path (fp32)
    mean_stage1<<<B_*MCH_, 256>>>(x);
    mean_stage2<<<(B_*D_)/256, 256>>>();
    temp_kernel<<<B_, 256>>>(Wt, bt);

    // normalize + head relayout
    norm_split<<<(BH_*S_*32)/256, 256>>>();

    // scores (fp16 out), top-k softmax (16-bit select), attn @ V
    scores_mma<<<dim3(S_/128, S_/128, BH_), 256>>>();
    topk_softmax<<<BH_*S_, 256>>>();
    av_mma<<<dim3(1, S_/128, BH_), 256>>>();

    // output projection + highway gate
    hgemm_bias<<<dim3(D_/128, M_/128), 256>>>(obsdh, Woh, bo, out2h, M_, D_, D_);
    finalize_kernel<<<(M_*D_/2)/256, 256>>>(x, out);
}

// round 7
// speedup vs baseline: 1.7235x; 1.0685x over previous
#include <cuda_runtime.h>
#include <cuda_fp16.h>
#include <math.h>

#define B_   2
#define S_   2048
#define D_   1024
#define H_   16
#define DH_  64
#define M_   (B_*S_)          // 4096 tokens
#define BH_  (B_*H_)          // 32
#define KK_  512              // top-k
#define MCH_ 16               // mean chunks

#define SA   40               // smem row stride (halves) for 32-col tiles
#define SBP  136              // smem row stride for 128-col B tiles
#define SBV  72               // smem row stride for 64-col V tiles
#define QST  72               // scores kernel: Q/K row stride (64 cols + pad)

// ---------------- scratch (static device memory; no allocations) ----------------
__device__ __half g_xh[M_*D_];
__device__ __half g_Wcat[D_*4*D_];         // packed [1024][4096] : Wq|Wk|Wv|Wg
__device__ float  g_bcat[4*D_];
__device__ __half g_Woh[D_*D_];
__device__ __half g_qkvgh[(size_t)M_*4*D_]; // [4096][4096] : q|k|v|gate
__device__ __half g_qnh[M_*D_];     // [BH][S][DH]
__device__ __half g_knh[M_*D_];     // [BH][S][DH]
__device__ __half g_vhh[M_*D_];     // [BH][S][DH]
__device__ __half g_obsdh[M_*D_];   // attention output in [B,S,D]
__device__ __half g_out2h[M_*D_];   // after Wo
__device__ __half g_scoresh[(size_t)BH_*S_*S_]; // 256MB fp16 scores (post-temp)
__device__ __half g_attnh[(size_t)BH_*S_*S_];   // 256MB fp16 attention weights
__device__ float  g_xpart[MCH_*B_*D_];
__device__ float  g_xmean[B_*D_];
__device__ float  g_temp[B_];

// ---------------- mma / ldmatrix helpers ----------------
__device__ __forceinline__ void mma_f16(float* d, const unsigned* a, unsigned b0, unsigned b1){
    asm volatile("mma.sync.aligned.m16n8k16.row.col.f32.f16.f16.f32 "
        "{%0,%1,%2,%3}, {%4,%5,%6,%7}, {%8,%9}, {%0,%1,%2,%3};\n"
        : "+f"(d[0]),"+f"(d[1]),"+f"(d[2]),"+f"(d[3])
        : "r"(a[0]),"r"(a[1]),"r"(a[2]),"r"(a[3]), "r"(b0),"r"(b1));
}
__device__ __forceinline__ void ldsm4(unsigned* r, const __half* p){
    unsigned addr = (unsigned)__cvta_generic_to_shared(p);
    asm volatile("ldmatrix.sync.aligned.m8n8.x4.shared.b16 {%0,%1,%2,%3}, [%4];\n"
        :"=r"(r[0]),"=r"(r[1]),"=r"(r[2]),"=r"(r[3]) : "r"(addr));
}
__device__ __forceinline__ void ldsm4t(unsigned* r, const __half* p){
    unsigned addr = (unsigned)__cvta_generic_to_shared(p);
    asm volatile("ldmatrix.sync.aligned.m8n8.x4.trans.shared.b16 {%0,%1,%2,%3}, [%4];\n"
        :"=r"(r[0]),"=r"(r[1]),"=r"(r[2]),"=r"(r[3]) : "r"(addr));
}

// ---------------- fp32 -> fp16 conversion ----------------
__global__ __launch_bounds__(256) void f2h_kernel(const float* __restrict__ in,
                                                  __half* __restrict__ out){
    int i = blockIdx.x*256 + threadIdx.x;
    float4 v = reinterpret_cast<const float4*>(in)[i];
    reinterpret_cast<__half2*>(out)[2*i]   = __floats2half2_rn(v.x, v.y);
    reinterpret_cast<__half2*>(out)[2*i+1] = __floats2half2_rn(v.z, v.w);
}

// pack FOUR 1024x1024 fp32 weights into [1024][4096] halves: Wq|Wk|Wv|Wg
__global__ __launch_bounds__(256) void f2h_pack4(const float* __restrict__ w0,
                                                 const float* __restrict__ w1,
                                                 const float* __restrict__ w2,
                                                 const float* __restrict__ w3){
    int gi = blockIdx.x*256 + threadIdx.x;
    int q = gi >> 18;
    int i = gi & 262143;
    const float* in = (q==0) ? w0 : (q==1) ? w1 : (q==2) ? w2 : w3;
    int row = i >> 8, c4 = (i & 255) * 4;
    float4 v = reinterpret_cast<const float4*>(in)[i];
    __half* o = g_Wcat + (size_t)row*4096 + q*1024 + c4;
    *(__half2*)&o[0] = __floats2half2_rn(v.x, v.y);
    *(__half2*)&o[2] = __floats2half2_rn(v.z, v.w);
}

__global__ __launch_bounds__(256) void pack_bias(const float* __restrict__ bq,
                                                 const float* __restrict__ bk,
                                                 const float* __restrict__ bv,
                                                 const float* __restrict__ bg){
    int idx = blockIdx.x*256 + threadIdx.x;
    int seg = idx >> 10, j = idx & 1023;
    float v = (seg==0) ? bq[j] : (seg==1) ? bk[j] : (seg==2) ? bv[j] : bg[j];
    g_bcat[idx] = v;
}

// ---------------- mean over sequence + temperature ----------------
__global__ __launch_bounds__(256) void mean_stage1(const float* __restrict__ x){
    int b  = blockIdx.x / MCH_;
    int ch = blockIdx.x % MCH_;
    int s0 = ch * (S_/MCH_);
    int tid = threadIdx.x;
    float acc[4] = {0.f,0.f,0.f,0.f};
    for (int s = s0; s < s0 + S_/MCH_; ++s){
        const float* xp = x + ((size_t)(b*S_+s))*D_;
        #pragma unroll
        for (int j = 0; j < 4; ++j) acc[j] += xp[tid + j*256];
    }
    #pragma unroll
    for (int j = 0; j < 4; ++j) g_xpart[((size_t)ch*B_ + b)*D_ + tid + j*256] = acc[j];
}

__global__ __launch_bounds__(256) void mean_stage2(){
    int idx = blockIdx.x*256 + threadIdx.x;
    int b = idx / D_, d = idx % D_;
    float s = 0.f;
    #pragma unroll
    for (int ch = 0; ch < MCH_; ++ch) s += g_xpart[((size_t)ch*B_ + b)*D_ + d];
    g_xmean[idx] = s * (1.0f/S_);
}

__global__ __launch_bounds__(256) void temp_kernel(const float* __restrict__ Wt,
                                                   const float* __restrict__ bt){
    __shared__ float red[256];
    int b = blockIdx.x, tid = threadIdx.x;
    float s = 0.f;
    for (int d = tid; d < D_; d += 256) s += g_xmean[b*D_ + d] * Wt[d];
    red[tid] = s; __syncthreads();
    for (int o = 128; o; o >>= 1){ if (tid < o) red[tid] += red[tid+o]; __syncthreads(); }
    if (tid == 0) g_temp[b] = 1.0f/(1.0f + expf(-(red[0] + bt[0]))) + 0.5f;
}

// ---------------- fp16 tensor-core GEMM: C(fp16) = A @ W + bias ----------------
__global__ __launch_bounds__(256) void hgemm_bias(const __half* __restrict__ A,
                                                  const __half* __restrict__ Bw,
                                                  const float* __restrict__ bias,
                                                  __half* __restrict__ C,
                                                  int M, int N, int K){
    __shared__ __half As[2][128*SA];
    __shared__ __half Bs[2][32*SBP];
    const int tid = threadIdx.x, lane = tid & 31, wid = tid >> 5;
    const int m0 = blockIdx.y*128, n0 = blockIdx.x*128;
    const int wm = (wid & 1)*64, wn = (wid >> 1)*32;
    const int KT = K >> 5;
    float acc[4][4][4] = {};

    const int ar = tid >> 2, ac = (tid & 3) << 3;
    const int br = tid >> 4, bc = (tid & 15) << 3;

    #pragma unroll
    for (int c = 0; c < 2; ++c){
        *(float4*)&As[0][(ar+c*64)*SA + ac] =
            *(const float4*)(A + (size_t)(m0+ar+c*64)*K + ac);
        *(float4*)&Bs[0][(br+c*16)*SBP + bc] =
            *(const float4*)(Bw + (size_t)(br+c*16)*N + n0 + bc);
    }
    __syncthreads();

    for (int kt = 0; kt < KT; ++kt){
        const int cur = kt & 1;
        float4 ra[2], rb[2];
        const bool nxt = (kt+1 < KT);
        if (nxt){
            int k0 = (kt+1) << 5;
            #pragma unroll
            for (int c = 0; c < 2; ++c){
                ra[c] = *(const float4*)(A + (size_t)(m0+ar+c*64)*K + k0 + ac);
                rb[c] = *(const float4*)(Bw + (size_t)(k0+br+c*16)*N + n0 + bc);
            }
        }
        #pragma unroll
        for (int ks = 0; ks < 2; ++ks){
            unsigned af[4][4], bf[2][4];
            #pragma unroll
            for (int mt = 0; mt < 4; ++mt)
                ldsm4(af[mt], &As[cur][(wm+mt*16+(lane&15))*SA + ks*16 + (lane>>4)*8]);
            #pragma unroll
            for (int g = 0; g < 2; ++g)
                ldsm4t(bf[g], &Bs[cur][(ks*16+(lane&15))*SBP + wn + g*16 + (lane>>4)*8]);
            #pragma unroll
            for (int mt = 0; mt < 4; ++mt)
                #pragma unroll
                for (int g = 0; g < 2; ++g){
                    mma_f16(acc[mt][2*g],   af[mt], bf[g][0], bf[g][1]);
                    mma_f16(acc[mt][2*g+1], af[mt], bf[g][2], bf[g][3]);
                }
        }
        if (nxt){
            #pragma unroll
            for (int c = 0; c < 2; ++c){
                *(float4*)&As[cur^1][(ar+c*64)*SA + ac] = ra[c];
                *(float4*)&Bs[cur^1][(br+c*16)*SBP + bc] = rb[c];
            }
        }
        __syncthreads();
    }

    #pragma unroll
    for (int mt = 0; mt < 4; ++mt){
        int r = m0 + wm + mt*16 + (lane >> 2);
        #pragma unroll
        for (int nt = 0; nt < 4; ++nt){
            int c = n0 + wn + nt*8 + (lane & 3)*2;
            float b0 = bias[c], b1 = bias[c+1];
            *(__half2*)&C[(size_t)r*N + c] =
                __floats2half2_rn(acc[mt][nt][0]+b0, acc[mt][nt][1]+b1);
            *(__half2*)&C[(size_t)(r+8)*N + c] =
                __floats2half2_rn(acc[mt][nt][2]+b0, acc[mt][nt][3]+b1);
        }
    }
}

// ---------------- head split + L2 normalize (q,k) + v relayout (from qkvg) ----------------
__global__ __launch_bounds__(256) void norm_split(){
    int gw   = (blockIdx.x*256 + threadIdx.x) >> 5;
    int lane = threadIdx.x & 31;
    int s  = gw & (S_-1);
    int bh = gw >> 11;
    int h  = bh & (H_-1), b = bh >> 4;
    size_t row = (size_t)(b*S_+s)*4096;
    int hc = h*DH_ + lane*2;
    size_t dst = (size_t)gw * DH_ + lane*2;

    float2 qv = __half22float2(*(const __half2*)(g_qkvgh + row + hc));
    float ss = qv.x*qv.x + qv.y*qv.y;
    #pragma unroll
    for (int o = 16; o; o >>= 1) ss += __shfl_xor_sync(0xFFFFFFFFu, ss, o);
    float inv = 1.0f / fmaxf(sqrtf(ss), 1e-12f);
    *(__half2*)(g_qnh + dst) = __floats2half2_rn(qv.x*inv, qv.y*inv);

    float2 kv = __half22float2(*(const __half2*)(g_qkvgh + row + 1024 + hc));
    ss = kv.x*kv.x + kv.y*kv.y;
    #pragma unroll
    for (int o = 16; o; o >>= 1) ss += __shfl_xor_sync(0xFFFFFFFFu, ss, o);
    inv = 1.0f / fmaxf(sqrtf(ss), 1e-12f);
    *(__half2*)(g_knh + dst) = __floats2half2_rn(kv.x*inv, kv.y*inv);

    *(__half2*)(g_vhh + dst) = *(const __half2*)(g_qkvgh + row + 2048 + hc);
}

// ---------------- scores v2: one block = 128 rows x full 2048 keys ----------------
// grid (16 m-tiles, 32 heads), 256 threads, A frags register-resident,
// K streamed through double-buffered smem. Same math/accumulation order as v1.
__global__ __launch_bounds__(256) void scores_mma(){
    extern __shared__ __half sm[];
    __half* Qs  = sm;                     // 128 x QST
    __half* Ksb = sm + 128*QST;           // 2 x 128 x QST
    const int bh = blockIdx.y, b = bh >> 4;
    const int m0 = blockIdx.x * 128;
    const __half* Qg = g_qnh + (size_t)bh*S_*DH_;
    const __half* Kg = g_knh + (size_t)bh*S_*DH_;
    const int tid = threadIdx.x, lane = tid & 31, wid = tid >> 5;
    const int wm = (wid & 1)*64, wn = (wid >> 1)*32;

    #pragma unroll
    for (int j = 0; j < 4; ++j){
        int idx = j*256 + tid;            // 1024 float4 = 128x64 halves
        int row = idx >> 3, c8 = (idx & 7) << 3;
        *(float4*)&Qs[row*QST + c8] = *(const float4*)(Qg + (size_t)(m0+row)*DH_ + c8);
        *(float4*)&Ksb[row*QST + c8] = *(const float4*)(Kg + (size_t)row*DH_ + c8);
    }
    __syncthreads();

    // preload all A fragments (K=64 -> 4 k-slices)
    unsigned af[4][4][4];
    #pragma unroll
    for (int ks = 0; ks < 4; ++ks)
        #pragma unroll
        for (int mt = 0; mt < 4; ++mt)
            ldsm4(af[ks][mt], &Qs[(wm+mt*16+(lane&15))*QST + ks*16 + (lane>>4)*8]);

    const float scl = 1.0f / g_temp[b];

    for (int c = 0; c < 16; ++c){
        __half* cur = Ksb + (c & 1)*(128*QST);
        __half* nb  = Ksb + ((c+1) & 1)*(128*QST);
        float4 pre[4];
        const bool nxt = (c+1 < 16);
        if (nxt){
            #pragma unroll
            for (int j = 0; j < 4; ++j){
                int idx = j*256 + tid;
                int row = idx >> 3, c8 = (idx & 7) << 3;
                pre[j] = *(const float4*)(Kg + (size_t)((c+1)*128+row)*DH_ + c8);
            }
        }
        float acc[4][4][4] = {};
        #pragma unroll
        for (int ks = 0; ks < 4; ++ks){
            unsigned bf[2][4];
            #pragma unroll
            for (int g = 0; g < 2; ++g)
                ldsm4(bf[g], &cur[(wn + g*16 + ((lane>>4)<<3) + (lane&7))*QST
                                  + ks*16 + ((lane>>3)&1)*8]);
            #pragma unroll
            for (int mt = 0; mt < 4; ++mt)
                #pragma unroll
                for (int g = 0; g < 2; ++g){
                    mma_f16(acc[mt][2*g],   af[ks][mt], bf[g][0], bf[g][1]);
                    mma_f16(acc[mt][2*g+1], af[ks][mt], bf[g][2], bf[g][3]);
                }
        }
        // epilogue: scale + fp16 store
        #pragma unroll
        for (int mt = 0; mt < 4; ++mt){
            int r = m0 + wm + mt*16 + (lane >> 2);
            #pragma unroll
            for (int nt = 0; nt < 4; ++nt){
                int col = c*128 + wn + nt*8 + (lane & 3)*2;
                *(__half2*)&g_scoresh[((size_t)bh*S_ + r)*S_ + col] =
                    __floats2half2_rn(acc[mt][nt][0]*scl, acc[mt][nt][1]*scl);
                *(__half2*)&g_scoresh[((size_t)bh*S_ + r + 8)*S_ + col] =
                    __floats2half2_rn(acc[mt][nt][2]*scl, acc[mt][nt][3]*scl);
            }
        }
        if (nxt){
            __syncthreads();   // everyone done reading nb's previous contents
            #pragma unroll
            for (int j = 0; j < 4; ++j){
                int idx = j*256 + tid;
                int row = idx >> 3, c8 = (idx & 7) << 3;
                *(float4*)&nb[row*QST + c8] = pre[j];
            }
            __syncthreads();   // nb visible to all
        }
    }
}

// ---------------- exact top-512 radix-select (16-bit keys, 2 passes) + softmax ----------------
__global__ __launch_bounds__(256) void topk_softmax(){
    const size_t row = blockIdx.x;
    const __half* sp = g_scoresh + row*(size_t)S_;
    __half* ap = g_attnh + row*(size_t)S_;
    __shared__ unsigned hist[256];
    __shared__ unsigned sufs[256];
    __shared__ unsigned wsum[8];
    __shared__ float fr[8];
    __shared__ unsigned s_bin, s_above;
    __shared__ float s_mx, s_sum;
    const int tid = threadIdx.x, lane = tid & 31, wid = tid >> 5;

    // vectorized load: 8 contiguous halves per thread
    int4 raw = *(const int4*)(sp + (size_t)tid*8);
    unsigned rw[4] = {(unsigned)raw.x, (unsigned)raw.y, (unsigned)raw.z, (unsigned)raw.w};
    float v[8]; unsigned key[8];
    #pragma unroll
    for (int i = 0; i < 8; ++i){
        unsigned u = (rw[i>>1] >> ((i&1)*16)) & 0xFFFFu;
        v[i] = __half2float(__ushort_as_half((unsigned short)u));
        key[i] = u ^ ((u & 0x8000u) ? 0xFFFFu : 0x8000u);
    }

    unsigned prefix = 0, remaining = KK_;
    #pragma unroll
    for (int pass = 0; pass < 2; ++pass){
        const int shift = 8 - pass*8;
        hist[tid] = 0; __syncthreads();
        unsigned pmask = (pass == 0) ? 0u : 0xFF00u;
        #pragma unroll
        for (int i = 0; i < 8; ++i)
            if ((key[i] & pmask) == prefix) atomicAdd(&hist[(key[i] >> shift) & 255], 1u);
        __syncthreads();
        unsigned x = hist[255 - tid];
        #pragma unroll
        for (int o = 1; o < 32; o <<= 1){
            unsigned t = __shfl_up_sync(0xFFFFFFFFu, x, o);
            if (lane >= o) x += t;
        }
        if (lane == 31) wsum[wid] = x;
        __syncthreads();
        if (tid < 8){
            unsigned w = wsum[tid];
            #pragma unroll
            for (int o = 1; o < 8; o <<= 1){
                unsigned t = __shfl_up_sync(0xFFu, w, o);
                if (tid >= o) w += t;
            }
            wsum[tid] = w;
        }
        __syncthreads();
        unsigned suf = x + (wid ? wsum[wid-1] : 0u);
        sufs[255 - tid] = suf;
        __syncthreads();
        unsigned Sb  = sufs[tid];
        unsigned Sb1 = (tid < 255) ? sufs[tid+1] : 0u;
        if (Sb >= remaining && Sb1 < remaining){ s_bin = (unsigned)tid; s_above = Sb1; }
        __syncthreads();
        remaining -= s_above;
        prefix |= (s_bin << shift);
        __syncthreads();
    }
    const unsigned T = prefix;

    float mx = -3.402823466e38f;
    #pragma unroll
    for (int i = 0; i < 8; ++i) mx = fmaxf(mx, v[i]);
    #pragma unroll
    for (int o = 16; o; o >>= 1) mx = fmaxf(mx, __shfl_xor_sync(0xFFFFFFFFu, mx, o));
    if (lane == 0) fr[wid] = mx;
    __syncthreads();
    if (tid == 0){
        float m = fr[0];
        #pragma unroll
        for (int j = 1; j < 8; ++j) m = fmaxf(m, fr[j]);
        s_mx = m;
    }
    __syncthreads();
    mx = s_mx;

    float e[8]; float ls = 0.f;
    #pragma unroll
    for (int i = 0; i < 8; ++i){
        e[i] = (key[i] >= T) ? expf(v[i] - mx) : 0.0f;
        ls += e[i];
    }
    #pragma unroll
    for (int o = 16; o; o >>= 1) ls += __shfl_xor_sync(0xFFFFFFFFu, ls, o);
    if (lane == 0) fr[wid] = ls;
    __syncthreads();
    if (tid == 0){
        float m = 0.f;
        #pragma unroll
        for (int j = 0; j < 8; ++j) m += fr[j];
        s_sum = m;
    }
    __syncthreads();
    const float inv = 1.0f / s_sum;

    // vectorized store
    unsigned ow[4];
    #pragma unroll
    for (int i = 0; i < 4; ++i){
        __half2 p = __floats2half2_rn(e[2*i]*inv, e[2*i+1]*inv);
        ow[i] = *(unsigned*)&p;
    }
    int4 o; o.x = (int)ow[0]; o.y = (int)ow[1]; o.z = (int)ow[2]; o.w = (int)ow[3];
    *(int4*)(ap + (size_t)tid*8) = o;
}

// ---------------- O = attn @ V  (fp16 mma) ----------------
__global__ __launch_bounds__(256) void av_mma(){
    const int bh = blockIdx.z;
    const int m0 = blockIdx.y*128;
    const __half* A = g_attnh + (size_t)bh*S_*S_;
    const __half* V = g_vhh   + (size_t)bh*S_*DH_;
    __shared__ __half As[2][128*SA];
    __shared__ __half Bs[2][32*SBV];
    const int tid = threadIdx.x, lane = tid & 31, wid = tid >> 5;
    const int wm = (wid & 3)*32, wn = (wid >> 2)*32;
    float acc[2][4][4] = {};

    const int ar = tid >> 2, ac = (tid & 3) << 3;
    const int br = tid >> 3, bc = (tid & 7) << 3;

    #pragma unroll
    for (int c = 0; c < 2; ++c)
        *(float4*)&As[0][(ar+c*64)*SA + ac] =
            *(const float4*)(A + (size_t)(m0+ar+c*64)*S_ + ac);
    *(float4*)&Bs[0][br*SBV + bc] = *(const float4*)(V + (size_t)br*DH_ + bc);
    __syncthreads();

    const int KT = S_ >> 5;
    for (int kt = 0; kt < KT; ++kt){
        const int cur = kt & 1;
        float4 ra[2], rb;
        const bool nxt = (kt+1 < KT);
        if (nxt){
            int k0 = (kt+1) << 5;
            #pragma unroll
            for (int c = 0; c < 2; ++c)
                ra[c] = *(const float4*)(A + (size_t)(m0+ar+c*64)*S_ + k0 + ac);
            rb = *(const float4*)(V + (size_t)(k0+br)*DH_ + bc);
        }
        #pragma unroll
        for (int ks = 0; ks < 2; ++ks){
            unsigned af[2][4], bf[2][4];
            #pragma unroll
            for (int mt = 0; mt < 2; ++mt)
                ldsm4(af[mt], &As[cur][(wm+mt*16+(lane&15))*SA + ks*16 + (lane>>4)*8]);
            #pragma unroll
            for (int g = 0; g < 2; ++g)
                ldsm4t(bf[g], &Bs[cur][(ks*16+(lane&15))*SBV + wn + g*16 + (lane>>4)*8]);
            #pragma unroll
            for (int mt = 0; mt < 2; ++mt)
                #pragma unroll
                for (int g = 0; g < 2; ++g){
                    mma_f16(acc[mt][2*g],   af[mt], bf[g][0], bf[g][1]);
                    mma_f16(acc[mt][2*g+1], af[mt], bf[g][2], bf[g][3]);
                }
        }
        if (nxt){
            #pragma unroll
            for (int c = 0; c < 2; ++c)
                *(float4*)&As[cur^1][(ar+c*64)*SA + ac] = ra[c];
            *(float4*)&Bs[cur^1][br*SBV + bc] = rb;
        }
        __syncthreads();
    }

    const int bb = bh >> 4, h = bh & (H_-1);
    #pragma unroll
    for (int mt = 0; mt < 2; ++mt){
        int s_idx = m0 + wm + mt*16 + (lane >> 2);
        size_t grow0 = (size_t)(bb*S_ + s_idx)*D_;
        size_t grow1 = (size_t)(bb*S_ + s_idx + 8)*D_;
        #pragma unroll
        for (int nt = 0; nt < 4; ++nt){
            int c = h*DH_ + wn + nt*8 + (lane & 3)*2;
            *(__half2*)&g_obsdh[grow0 + c] = __floats2half2_rn(acc[mt][nt][0], acc[mt][nt][1]);
            *(__half2*)&g_obsdh[grow1 + c] = __floats2half2_rn(acc[mt][nt][2], acc[mt][nt][3]);
        }
    }
}

// ---------------- highway gating ----------------
__global__ __launch_bounds__(256) void finalize_kernel(const float* __restrict__ x,
                                                       float* __restrict__ out){
    int i = blockIdx.x*256 + threadIdx.x;
    int p = 2*i;
    int r = p >> 10, cb = p & 1023;
    float2 xv = reinterpret_cast<const float2*>(x)[i];
    float2 gv = __half22float2(*(const __half2*)&g_qkvgh[(size_t)r*4096 + 3072 + cb]);
    float2 ov = __half22float2(reinterpret_cast<const __half2*>(g_out2h)[i]);
    float2 rr;
    float g;
    g = 1.0f/(1.0f+expf(-gv.x)); rr.x = g*ov.x + (1.0f-g)*xv.x;
    g = 1.0f/(1.0f+expf(-gv.y)); rr.y = g*ov.y + (1.0f-g)*xv.y;
    reinterpret_cast<float2*>(out)[i] = rr;
}

// ---------------- launch ----------------
extern "C" void kernel_launch(void* const* d_in, const int* in_sizes, int n_in,
                              void* d_out, int out_size){
    (void)in_sizes; (void)n_in; (void)out_size;
    const float* x  = (const float*)d_in[0];
    const float* Wq = (const float*)d_in[1];  const float* bq = (const float*)d_in[2];
    const float* Wk = (const float*)d_in[3];  const float* bk = (const float*)d_in[4];
    const float* Wv = (const float*)d_in[5];  const float* bv = (const float*)d_in[6];
    const float* Wo = (const float*)d_in[7];  const float* bo = (const float*)d_in[8];
    const float* Wt = (const float*)d_in[9];  const float* bt = (const float*)d_in[10];
    const float* Wg = (const float*)d_in[11]; const float* bg = (const float*)d_in[12];
    float* out = (float*)d_out;

    __half *xh,*Wcat,*Woh,*qkvgh,*obsdh,*out2h;
    float *bcat;
    cudaGetSymbolAddress((void**)&xh,    g_xh);
    cudaGetSymbolAddress((void**)&Wcat,  g_Wcat);
    cudaGetSymbolAddress((void**)&bcat,  g_bcat);
    cudaGetSymbolAddress((void**)&Woh,   g_Woh);
    cudaGetSymbolAddress((void**)&qkvgh, g_qkvgh);
    cudaGetSymbolAddress((void**)&obsdh, g_obsdh);
    cudaGetSymbolAddress((void**)&out2h, g_out2h);

    const int SC_SMEM = 3*128*QST*(int)sizeof(__half);   // 55296 bytes
    cudaFuncSetAttribute(scores_mma, cudaFuncAttributeMaxDynamicSharedMemorySize, SC_SMEM);

    pack_bias<<<16, 256>>>(bq, bk, bv, bg);                        // 0
    f2h_kernel<<<(M_*D_)/1024, 256>>>(x, xh);                      // 1
    f2h_pack4<<<4*(D_*D_)/1024, 256>>>(Wq, Wk, Wv, Wg);            // 2

    // launch 3: fused QKVG projection (profiled by ncu)
    hgemm_bias<<<dim3(4096/128, M_/128), 256>>>(xh, Wcat, bcat, qkvgh, M_, 4096, D_);

    f2h_kernel<<<(D_*D_)/1024, 256>>>(Wo, Woh);

    // temperature path (fp32)
    mean_stage1<<<B_*MCH_, 256>>>(x);
    mean_stage2<<<(B_*D_)/256, 256>>>();
    temp_kernel<<<B_, 256>>>(Wt, bt);

    // normalize + head relayout
    norm_split<<<(BH_*S_*32)/256, 256>>>();

    // scores v2 (block-per-row-tile, K streamed), top-k softmax, attn @ V
    scores_mma<<<dim3(S_/128, BH_), 256, SC_SMEM>>>();
    topk_softmax<<<BH_*S_, 256>>>();
    av_mma<<<dim3(1, S_/128, BH_), 256>>>();

    // output projection + highway gate
    hgemm_bias<<<dim3(D_/128, M_/128), 256>>>(obsdh, Woh, bo, out2h, M_, D_, D_);
    finalize_kernel<<<(M_*D_/2)/256, 256>>>(x, out);
}